// round 11
// baseline (speedup 1.0000x reference)
#include <cuda_runtime.h>
#include <cuda_fp16.h>
#include <cstdint>

#define N_NODES 100000
#define N_EDGES 3200000
#define IN_CH   500
#define HID     64
#define OUT_CH  40
#define K_HOPS  10
#define ROWC    5    // 16B chunks per packed feature row (80B = 40 half)

// ---------------- scratch ----------------
__device__ int    g_deg[N_NODES];
__device__ int    g_fill[N_NODES];
__device__ int    g_rowptr[N_NODES + 1];
__device__ float  g_dinv[N_NODES];
__device__ int    g_col[N_EDGES];             // CSR col (src); weight folded into features
__device__ uint4  g_curh[N_NODES * ROWC];     // scaled fp16 features s = dinv*x (ping)
__device__ uint4  g_nexth[N_NODES * ROWC];    // (pong)
__device__ float4 g_hidden4[N_NODES * 10];    // fp32 hidden accumulator
__device__ int    g_bsum[128];

__device__ __forceinline__ int clamp_node(int v) {
    return v < 0 ? 0 : (v >= N_NODES ? N_NODES - 1 : v);
}

__device__ __forceinline__ void unpack8(uint4 u, float* f) {
    float2 a = __half22float2(*(__half2*)&u.x);
    float2 b = __half22float2(*(__half2*)&u.y);
    float2 c = __half22float2(*(__half2*)&u.z);
    float2 d = __half22float2(*(__half2*)&u.w);
    f[0] = a.x; f[1] = a.y; f[2] = b.x; f[3] = b.y;
    f[4] = c.x; f[5] = c.y; f[6] = d.x; f[7] = d.y;
}

__device__ __forceinline__ uint4 pack8(const float* f) {
    uint4 u;
    *(__half2*)&u.x = __floats2half2_rn(f[0], f[1]);
    *(__half2*)&u.y = __floats2half2_rn(f[2], f[3]);
    *(__half2*)&u.z = __floats2half2_rn(f[4], f[5]);
    *(__half2*)&u.w = __floats2half2_rn(f[6], f[7]);
    return u;
}

// ---------------- stem: BM=128, BN=64, BK=32; HFMA2, kp-major A tile ----------------
// phase1 smem (half2): As2T[16][136] kp-major (2176) + Bs2[16][65] (1040)
// phase2 (fp32): hs[128][65] + W2s[40][65]
__global__ void stem_kernel(const float* __restrict__ x, const float* __restrict__ W1,
                            const float* __restrict__ b1, const float* __restrict__ W2,
                            const float* __restrict__ b2, const float* __restrict__ gamma,
                            const float* __restrict__ beta, const float* __restrict__ mean,
                            const float* __restrict__ var) {
    __shared__ float buf[10920];
    __shared__ float Ac[HID], Bc[HID], b2s[OUT_CH];
    __half2* As2 = (__half2*)buf;               // [16][136] kp-major = 2176 slots
    __half2* Bs2 = (__half2*)buf + 2176;        // [16][65]  = 1040 slots
    float* hs  = buf;                           // [128][65] (phase 2)
    float* W2s = buf + 8320;                    // [40][65]

    const int t = threadIdx.x;        // 256 threads
    const int node0 = blockIdx.x * 128;
    const int tx = t & 15, ty = t >> 4;

    if (t < HID) {
        float A = gamma[t] * rsqrtf(var[t] + 1e-5f);
        Ac[t] = A;
        Bc[t] = (b1[t] - mean[t]) * A + beta[t];
    }
    if (t < OUT_CH) b2s[t] = b2[t];

    float acc[8][4];
#pragma unroll
    for (int r = 0; r < 8; r++)
#pragma unroll
        for (int c = 0; c < 4; c++) acc[r][c] = 0.f;

    const int arow = t >> 1;            // 0..127
    const int akp0 = (t & 1) * 8;       // half2-k offset 0 or 8
    const int bh = t & 63;              // hid
    const int bkp0 = (t >> 6) * 4;      // half2-k rows [bkp0, bkp0+4)

    for (int kk = 0; kk < IN_CH; kk += 32) {
        // load As2T: thread -> row arow, half2-k [akp0, akp0+8), kp-major layout
        {
            int gn = node0 + arow;
            const float* xr = x + (size_t)gn * IN_CH + kk + akp0 * 2;
#pragma unroll
            for (int j = 0; j < 8; j++) {
                int col = kk + (akp0 + j) * 2;
                float2 v = make_float2(0.f, 0.f);
                if (gn < N_NODES && col < IN_CH) v = *(const float2*)(xr + 2 * j);
                As2[(akp0 + j) * 136 + arow] = __float22half2_rn(v);
            }
        }
        // load Bs2: thread -> hid bh, half2-k rows [bkp0, bkp0+4)
        {
            const float* wr = W1 + (size_t)bh * IN_CH + kk + bkp0 * 2;
#pragma unroll
            for (int j = 0; j < 4; j++) {
                int col = kk + (bkp0 + j) * 2;
                float2 v = make_float2(0.f, 0.f);
                if (col < IN_CH) v = *(const float2*)(wr + 2 * j);
                Bs2[(bkp0 + j) * 65 + bh] = __float22half2_rn(v);
            }
        }
        __syncthreads();
        __half2 acc2[8][4];
#pragma unroll
        for (int r = 0; r < 8; r++)
#pragma unroll
            for (int c = 0; c < 4; c++) acc2[r][c] = __float2half2_rn(0.f);
#pragma unroll
        for (int kp = 0; kp < 16; kp++) {
            __half2 a2[8], b2v[4];
            // 8 row-consecutive half2 -> 2x LDS.128
#pragma unroll
            for (int r = 0; r < 8; r++) a2[r] = As2[kp * 136 + ty * 8 + r];
#pragma unroll
            for (int c = 0; c < 4; c++) b2v[c] = Bs2[kp * 65 + tx * 4 + c];
#pragma unroll
            for (int r = 0; r < 8; r++)
#pragma unroll
                for (int c = 0; c < 4; c++) acc2[r][c] = __hfma2(a2[r], b2v[c], acc2[r][c]);
        }
        // flush fp16 pair-sums into fp32 accumulators (per 32-k tile)
#pragma unroll
        for (int r = 0; r < 8; r++)
#pragma unroll
            for (int c = 0; c < 4; c++) {
                float2 f = __half22float2(acc2[r][c]);
                acc[r][c] += f.x + f.y;
            }
        __syncthreads();
    }
    // BN + relu -> hs
#pragma unroll
    for (int r = 0; r < 8; r++)
#pragma unroll
        for (int c = 0; c < 4; c++) {
            int hd = tx * 4 + c;
            float v = acc[r][c] * Ac[hd] + Bc[hd];
            hs[(ty * 8 + r) * 65 + hd] = fmaxf(v, 0.f);
        }
    for (int idx = t; idx < OUT_CH * HID; idx += 256)
        W2s[(idx >> 6) * 65 + (idx & 63)] = W2[idx];
    __syncthreads();

    // phase 2: z = hs @ W2^T (fp32)
    const int n = t >> 1, ob = (t & 1) * 20;
    float outv[20];
#pragma unroll
    for (int j = 0; j < 20; j++) outv[j] = b2s[ob + j];
#pragma unroll 8
    for (int c = 0; c < HID; c++) {
        float hv = hs[n * 65 + c];
#pragma unroll
        for (int j = 0; j < 20; j++) outv[j] += hv * W2s[(ob + j) * 65 + c];
    }
    int gn = node0 + n;
    if (gn < N_NODES) {
        const float di = g_dinv[gn];
        __half2* dst = (__half2*)g_curh;   // packed: 20 half2 per node
#pragma unroll
        for (int j = 0; j < 10; j++)
            dst[(size_t)gn * 20 + ob / 2 + j] =
                __floats2half2_rn(di * outv[2 * j], di * outv[2 * j + 1]);
    }
}

// ---------------- CSR build ----------------
__global__ void zero_kernel() {
    int i = blockIdx.x * blockDim.x + threadIdx.x;
    if (i < N_NODES) { g_deg[i] = 1; g_fill[i] = 0; }  // 1 = self loop
}

// int4 edge loads: 4 edges per thread
__global__ void hist_kernel(const int4* __restrict__ dst4) {
    int e4 = blockIdx.x * blockDim.x + threadIdx.x;
    if (e4 < N_EDGES / 4) {
        int4 d = dst4[e4];
        atomicAdd(&g_deg[clamp_node(d.x)], 1);
        atomicAdd(&g_deg[clamp_node(d.y)], 1);
        atomicAdd(&g_deg[clamp_node(d.z)], 1);
        atomicAdd(&g_deg[clamp_node(d.w)], 1);
    }
}

__device__ __forceinline__ int block_incl_scan(int v, int* warpSums) {
    int lane = threadIdx.x & 31, wid = threadIdx.x >> 5;
#pragma unroll
    for (int o = 1; o < 32; o <<= 1) {
        int nv = __shfl_up_sync(0xFFFFFFFFu, v, o);
        if (lane >= o) v += nv;
    }
    if (lane == 31) warpSums[wid] = v;
    __syncthreads();
    if (wid == 0) {
        int s = (lane < (int)(blockDim.x >> 5)) ? warpSums[lane] : 0;
#pragma unroll
        for (int o = 1; o < 32; o <<= 1) {
            int nv = __shfl_up_sync(0xFFFFFFFFu, s, o);
            if (lane >= o) s += nv;
        }
        warpSums[lane] = s;
    }
    __syncthreads();
    if (wid > 0) v += warpSums[wid - 1];
    return v;
}

__global__ void scan1_kernel() {
    __shared__ int ws[32];
    int i = blockIdx.x * 1024 + threadIdx.x;
    int v = (i < N_NODES) ? (g_deg[i] - 1) : 0;
    int incl = block_incl_scan(v, ws);
    if (i < N_NODES) g_rowptr[i] = incl - v;
    if (threadIdx.x == 1023) g_bsum[blockIdx.x] = incl;
}

__global__ void scan2_kernel(int nb) {
    __shared__ int s[128];
    int i = threadIdx.x;
    int v = (i < nb) ? g_bsum[i] : 0;
    s[i] = v;
    __syncthreads();
    for (int o = 1; o < 128; o <<= 1) {
        int t2 = (i >= o) ? s[i - o] : 0;
        __syncthreads();
        s[i] += t2;
        __syncthreads();
    }
    g_bsum[i] = s[i] - v;
}

__global__ void scan3_kernel() {
    int i = blockIdx.x * blockDim.x + threadIdx.x;
    if (i < N_NODES) {
        g_rowptr[i] += g_bsum[i >> 10];
        g_dinv[i] = rsqrtf((float)g_deg[i]);
    }
    if (i == 0) g_rowptr[N_NODES] = N_EDGES;
}

__global__ void fill_kernel(const int4* __restrict__ src4, const int4* __restrict__ dst4) {
    int e4 = blockIdx.x * blockDim.x + threadIdx.x;
    if (e4 < N_EDGES / 4) {
        int4 s4 = src4[e4];
        int4 d4 = dst4[e4];
        int ss[4] = {clamp_node(s4.x), clamp_node(s4.y), clamp_node(s4.z), clamp_node(s4.w)};
        int dd[4] = {clamp_node(d4.x), clamp_node(d4.y), clamp_node(d4.z), clamp_node(d4.w)};
#pragma unroll
        for (int j = 0; j < 4; j++) {
            int p = g_rowptr[dd[j]] + atomicAdd(&g_fill[dd[j]], 1);
            if (p >= 0 && p < N_EDGES) g_col[p] = ss[j];
        }
    }
}

// ---------------- propagation: warp per node; 30-edge batches, 5 independent gathers ----------------
template <bool FIRST, bool LAST>
__global__ void prop_kernel(float* __restrict__ out, const float* __restrict__ temp, int k) {
    const uint4* __restrict__ cur = (k & 1) ? g_nexth : g_curh;
    uint4* __restrict__ next = (k & 1) ? g_curh : g_nexth;
    const int warp = (blockIdx.x * blockDim.x + threadIdx.x) >> 5;
    const int lane = threadIdx.x & 31;
    if (warp >= N_NODES) return;
    const int i = warp;
    const int g = lane / 5;          // 0..5 edge group (lane 30,31 idle)
    const int sub = lane - g * 5;    // 0..4 chunk
    const bool grp = (lane < 30);
    const int start = g_rowptr[i], end = g_rowptr[i + 1];
    const float di = g_dinv[i];

    float c[8], acc[8];
#pragma unroll
    for (int j = 0; j < 8; j++) { c[j] = 0.f; acc[j] = 0.f; }
    if (lane < 5) {
        uint4 u = cur[(size_t)i * ROWC + lane];
        unpack8(u, c);
#pragma unroll
        for (int j = 0; j < 8; j++) acc[j] = c[j];   // self term s_i
    }

    const int gl = (g < 6) ? g : 0;
    const int subc = (sub < 5) ? sub : 0;
    int e0 = start;

    for (; e0 + 30 <= end; e0 += 30) {
        int col = 0;
        if (lane < 30) col = g_col[e0 + lane];
        int srcs[5];
#pragma unroll
        for (int it = 0; it < 5; it++)
            srcs[it] = __shfl_sync(0xFFFFFFFFu, col, it * 6 + gl);
        uint4 us[5];
#pragma unroll
        for (int it = 0; it < 5; it++)
            us[it] = cur[(size_t)srcs[it] * ROWC + subc];
#pragma unroll
        for (int it = 0; it < 5; it++) {
            float v[8];
            unpack8(us[it], v);
            if (grp) {
#pragma unroll
                for (int j = 0; j < 8; j++) acc[j] += v[j];
            }
        }
    }
    for (; e0 < end; e0 += 6) {
        int col = 0;
        if (lane < 6) {
            int li = e0 + lane;
            col = g_col[li < end ? li : end - 1];
        }
        int src = __shfl_sync(0xFFFFFFFFu, col, gl);
        float wv = (grp && (e0 + g < end)) ? 1.f : 0.f;
        uint4 u = cur[(size_t)src * ROWC + subc];
        float v[8];
        unpack8(u, v);
#pragma unroll
        for (int j = 0; j < 8; j++) acc[j] += wv * v[j];
    }

    // reduce 6 groups (stride-5 lanes) -> lanes 0..4
#pragma unroll
    for (int j = 0; j < 8; j++) {
        float v = acc[j];
        v += __shfl_down_sync(0xFFFFFFFFu, v, 15);
        float t1 = __shfl_down_sync(0xFFFFFFFFu, v, 5);
        float t2 = __shfl_down_sync(0xFFFFFFFFu, v, 10);
        acc[j] = v + t1 + t2;
    }

    const float tk = temp[k + 1];
    float h[8];
#pragma unroll
    for (int j = 0; j < 8; j++) h[j] = 0.f;
    if (lane < 5) {
#pragma unroll
        for (int j = 0; j < 8; j++) acc[j] *= di;         // nv = di * (sum + s_i)
        if (FIRST) {
            const float t0z = temp[0] / di;                // z = s / di
#pragma unroll
            for (int j = 0; j < 8; j++) h[j] = t0z * c[j] + tk * acc[j];
        } else {
            float4 a = g_hidden4[i * 10 + lane * 2];
            float4 b = g_hidden4[i * 10 + lane * 2 + 1];
            h[0] = a.x + tk * acc[0]; h[1] = a.y + tk * acc[1];
            h[2] = a.z + tk * acc[2]; h[3] = a.w + tk * acc[3];
            h[4] = b.x + tk * acc[4]; h[5] = b.y + tk * acc[5];
            h[6] = b.z + tk * acc[6]; h[7] = b.w + tk * acc[7];
        }
        if (!LAST) {
            float sc[8];
#pragma unroll
            for (int j = 0; j < 8; j++) sc[j] = di * acc[j];   // s' = di * nv
            next[(size_t)i * ROWC + lane] = pack8(sc);
            g_hidden4[i * 10 + lane * 2]     = make_float4(h[0], h[1], h[2], h[3]);
            g_hidden4[i * 10 + lane * 2 + 1] = make_float4(h[4], h[5], h[6], h[7]);
        }
    }
    if (LAST) {
        float m = -1e30f;
        if (lane < 5) {
#pragma unroll
            for (int j = 0; j < 8; j++) m = fmaxf(m, h[j]);
        }
#pragma unroll
        for (int o = 1; o < 8; o <<= 1) m = fmaxf(m, __shfl_xor_sync(0xFFFFFFFFu, m, o));
        float s = 0.f;
        if (lane < 5) {
#pragma unroll
            for (int j = 0; j < 8; j++) s += expf(h[j] - m);
        }
#pragma unroll
        for (int o = 1; o < 8; o <<= 1) s += __shfl_xor_sync(0xFFFFFFFFu, s, o);
        const float lse = m + logf(s);
        if (lane < 5) {
            float4* o4 = (float4*)(out + (size_t)i * OUT_CH + lane * 8);
            o4[0] = make_float4(h[0] - lse, h[1] - lse, h[2] - lse, h[3] - lse);
            o4[1] = make_float4(h[4] - lse, h[5] - lse, h[6] - lse, h[7] - lse);
        }
    }
}

// ---------------- launch: kernel launches ONLY ----------------
extern "C" void kernel_launch(void* const* d_in, const int* in_sizes, int n_in,
                              void* d_out, int out_size) {
    const float* x    = (const float*)d_in[0];
    const int*   ei   = (const int*)d_in[1];  // [2, N_EDGES] int32
    const float* W1   = (const float*)d_in[2];
    const float* b1   = (const float*)d_in[3];
    const float* W2   = (const float*)d_in[4];
    const float* b2   = (const float*)d_in[5];
    const float* gam  = (const float*)d_in[6];
    const float* bet  = (const float*)d_in[7];
    const float* mea  = (const float*)d_in[8];
    const float* var  = (const float*)d_in[9];
    const float* temp = (const float*)d_in[10];
    float* out = (float*)d_out;
    const int4* src4 = (const int4*)ei;
    const int4* dst4 = (const int4*)(ei + N_EDGES);

    // CSR first (stem needs g_dinv)
    zero_kernel<<<(N_NODES + 255) / 256, 256>>>();
    hist_kernel<<<(N_EDGES / 4 + 255) / 256, 256>>>(dst4);
    const int nb = (N_NODES + 1023) / 1024;  // 98
    scan1_kernel<<<nb, 1024>>>();
    scan2_kernel<<<1, 128>>>(nb);
    scan3_kernel<<<(N_NODES + 255) / 256, 256>>>();
    fill_kernel<<<(N_EDGES / 4 + 255) / 256, 256>>>(src4, dst4);

    stem_kernel<<<(N_NODES + 127) / 128, 256>>>(x, W1, b1, W2, b2, gam, bet, mea, var);

    const int pgrid = (N_NODES * 32 + 255) / 256;
    prop_kernel<true, false><<<pgrid, 256>>>(nullptr, temp, 0);
    for (int k = 1; k < K_HOPS - 1; k++)
        prop_kernel<false, false><<<pgrid, 256>>>(nullptr, temp, k);
    prop_kernel<false, true><<<pgrid, 256>>>(out, temp, K_HOPS - 1);
}

// round 12
// speedup vs baseline: 1.5407x; 1.5407x over previous
#include <cuda_runtime.h>
#include <cuda_fp16.h>
#include <cstdint>

#define N_NODES 100000
#define N_EDGES 3200000
#define IN_CH   500
#define HID     64
#define OUT_CH  40
#define K_HOPS  10
#define ROWC    5    // 16B chunks per packed feature row (80B = 40 half)

// ---------------- scratch ----------------
__device__ int    g_deg[N_NODES];
__device__ int    g_fill[N_NODES];
__device__ int    g_rowptr[N_NODES + 1];
__device__ float  g_dinv[N_NODES];
__device__ int    g_col[N_EDGES];             // CSR col (src); weight folded into features
__device__ uint4  g_curh[N_NODES * ROWC];     // scaled fp16 features s = dinv*x (ping)
__device__ uint4  g_nexth[N_NODES * ROWC];    // (pong)
__device__ float4 g_hidden4[N_NODES * 10];    // fp32 hidden accumulator
__device__ int    g_bsum[128];

__device__ __forceinline__ int clamp_node(int v) {
    return v < 0 ? 0 : (v >= N_NODES ? N_NODES - 1 : v);
}

__device__ __forceinline__ void unpack8(uint4 u, float* f) {
    float2 a = __half22float2(*(__half2*)&u.x);
    float2 b = __half22float2(*(__half2*)&u.y);
    float2 c = __half22float2(*(__half2*)&u.z);
    float2 d = __half22float2(*(__half2*)&u.w);
    f[0] = a.x; f[1] = a.y; f[2] = b.x; f[3] = b.y;
    f[4] = c.x; f[5] = c.y; f[6] = d.x; f[7] = d.y;
}

__device__ __forceinline__ uint4 pack8(const float* f) {
    uint4 u;
    *(__half2*)&u.x = __floats2half2_rn(f[0], f[1]);
    *(__half2*)&u.y = __floats2half2_rn(f[2], f[3]);
    *(__half2*)&u.z = __floats2half2_rn(f[4], f[5]);
    *(__half2*)&u.w = __floats2half2_rn(f[6], f[7]);
    return u;
}

// ---------------- stem: BM=128, BN=64, BK=32; half2 HFMA2 inner loop ----------------
// phase1 smem (half2): As2[128][17] row-major (2176) + Bs2[16][68] (1088, 16B-aligned rows)
// phase2 (fp32): hs[128][65] + W2s[40][65]
__global__ void stem_kernel(const float* __restrict__ x, const float* __restrict__ W1,
                            const float* __restrict__ b1, const float* __restrict__ W2,
                            const float* __restrict__ b2, const float* __restrict__ gamma,
                            const float* __restrict__ beta, const float* __restrict__ mean,
                            const float* __restrict__ var) {
    __shared__ float buf[10920];
    __shared__ float Ac[HID], Bc[HID], b2s[OUT_CH];
    __half2* As2 = (__half2*)buf;               // [128][17] = 2176 slots
    __half2* Bs2 = (__half2*)buf + 2176;        // [16][68]  = 1088 slots (aligned rows)
    float* hs  = buf;                           // [128][65] (phase 2)
    float* W2s = buf + 8320;                    // [40][65]

    const int t = threadIdx.x;        // 256 threads
    const int node0 = blockIdx.x * 128;
    const int tx = t & 15, ty = t >> 4;

    if (t < HID) {
        float A = gamma[t] * rsqrtf(var[t] + 1e-5f);
        Ac[t] = A;
        Bc[t] = (b1[t] - mean[t]) * A + beta[t];
    }
    if (t < OUT_CH) b2s[t] = b2[t];

    float acc[8][4];
#pragma unroll
    for (int r = 0; r < 8; r++)
#pragma unroll
        for (int c = 0; c < 4; c++) acc[r][c] = 0.f;

    const int arow = t >> 1;            // 0..127
    const int akp0 = (t & 1) * 8;       // half2-k offset 0 or 8
    const int bh = t & 63;              // hid
    const int bkp0 = (t >> 6) * 4;      // half2-k rows [bkp0, bkp0+4)

    for (int kk = 0; kk < IN_CH; kk += 32) {
        // load As2: thread -> row arow, half2 cols [akp0, akp0+8)
        {
            int gn = node0 + arow;
            const float* xr = x + (size_t)gn * IN_CH + kk + akp0 * 2;
            __half2* dstA = As2 + arow * 17 + akp0;
#pragma unroll
            for (int j = 0; j < 8; j++) {
                int col = kk + (akp0 + j) * 2;
                float2 v = make_float2(0.f, 0.f);
                if (gn < N_NODES && col < IN_CH) v = *(const float2*)(xr + 2 * j);
                dstA[j] = __float22half2_rn(v);
            }
        }
        // load Bs2: thread -> hid bh, half2-k rows [bkp0, bkp0+4)
        {
            const float* wr = W1 + (size_t)bh * IN_CH + kk + bkp0 * 2;
#pragma unroll
            for (int j = 0; j < 4; j++) {
                int col = kk + (bkp0 + j) * 2;
                float2 v = make_float2(0.f, 0.f);
                if (col < IN_CH) v = *(const float2*)(wr + 2 * j);
                Bs2[(bkp0 + j) * 68 + bh] = __float22half2_rn(v);
            }
        }
        __syncthreads();
        __half2 acc2[8][4];
#pragma unroll
        for (int r = 0; r < 8; r++)
#pragma unroll
            for (int c = 0; c < 4; c++) acc2[r][c] = __float2half2_rn(0.f);
#pragma unroll
        for (int kp = 0; kp < 16; kp++) {
            __half2 a2[8], b2v[4];
#pragma unroll
            for (int r = 0; r < 8; r++) a2[r] = As2[(ty * 8 + r) * 17 + kp];
            // 4 consecutive half2 at 16B-aligned address -> LDS.128
#pragma unroll
            for (int c = 0; c < 4; c++) b2v[c] = Bs2[kp * 68 + tx * 4 + c];
#pragma unroll
            for (int r = 0; r < 8; r++)
#pragma unroll
                for (int c = 0; c < 4; c++) acc2[r][c] = __hfma2(a2[r], b2v[c], acc2[r][c]);
        }
        // flush fp16 pair-sums into fp32 accumulators (per 32-k tile)
#pragma unroll
        for (int r = 0; r < 8; r++)
#pragma unroll
            for (int c = 0; c < 4; c++) {
                float2 f = __half22float2(acc2[r][c]);
                acc[r][c] += f.x + f.y;
            }
        __syncthreads();
    }
    // BN + relu -> hs
#pragma unroll
    for (int r = 0; r < 8; r++)
#pragma unroll
        for (int c = 0; c < 4; c++) {
            int hd = tx * 4 + c;
            float v = acc[r][c] * Ac[hd] + Bc[hd];
            hs[(ty * 8 + r) * 65 + hd] = fmaxf(v, 0.f);
        }
    for (int idx = t; idx < OUT_CH * HID; idx += 256)
        W2s[(idx >> 6) * 65 + (idx & 63)] = W2[idx];
    __syncthreads();

    // phase 2: z = hs @ W2^T (fp32)
    const int n = t >> 1, ob = (t & 1) * 20;
    float outv[20];
#pragma unroll
    for (int j = 0; j < 20; j++) outv[j] = b2s[ob + j];
#pragma unroll 8
    for (int c = 0; c < HID; c++) {
        float hv = hs[n * 65 + c];
#pragma unroll
        for (int j = 0; j < 20; j++) outv[j] += hv * W2s[(ob + j) * 65 + c];
    }
    int gn = node0 + n;
    if (gn < N_NODES) {
        const float di = g_dinv[gn];
        __half2* dst = (__half2*)g_curh;   // packed: 20 half2 per node
#pragma unroll
        for (int j = 0; j < 10; j++)
            dst[(size_t)gn * 20 + ob / 2 + j] =
                __floats2half2_rn(di * outv[2 * j], di * outv[2 * j + 1]);
    }
}

// ---------------- CSR build (scalar edge loads — R10 known-good) ----------------
__global__ void zero_kernel() {
    int i = blockIdx.x * blockDim.x + threadIdx.x;
    if (i < N_NODES) { g_deg[i] = 1; g_fill[i] = 0; }  // 1 = self loop
}

__global__ void hist_kernel(const int* __restrict__ dst) {
    int e = blockIdx.x * blockDim.x + threadIdx.x;
    if (e < N_EDGES) atomicAdd(&g_deg[clamp_node(dst[e])], 1);
}

__device__ __forceinline__ int block_incl_scan(int v, int* warpSums) {
    int lane = threadIdx.x & 31, wid = threadIdx.x >> 5;
#pragma unroll
    for (int o = 1; o < 32; o <<= 1) {
        int nv = __shfl_up_sync(0xFFFFFFFFu, v, o);
        if (lane >= o) v += nv;
    }
    if (lane == 31) warpSums[wid] = v;
    __syncthreads();
    if (wid == 0) {
        int s = (lane < (int)(blockDim.x >> 5)) ? warpSums[lane] : 0;
#pragma unroll
        for (int o = 1; o < 32; o <<= 1) {
            int nv = __shfl_up_sync(0xFFFFFFFFu, s, o);
            if (lane >= o) s += nv;
        }
        warpSums[lane] = s;
    }
    __syncthreads();
    if (wid > 0) v += warpSums[wid - 1];
    return v;
}

__global__ void scan1_kernel() {
    __shared__ int ws[32];
    int i = blockIdx.x * 1024 + threadIdx.x;
    int v = (i < N_NODES) ? (g_deg[i] - 1) : 0;
    int incl = block_incl_scan(v, ws);
    if (i < N_NODES) g_rowptr[i] = incl - v;
    if (threadIdx.x == 1023) g_bsum[blockIdx.x] = incl;
}

__global__ void scan2_kernel(int nb) {
    __shared__ int s[128];
    int i = threadIdx.x;
    int v = (i < nb) ? g_bsum[i] : 0;
    s[i] = v;
    __syncthreads();
    for (int o = 1; o < 128; o <<= 1) {
        int t2 = (i >= o) ? s[i - o] : 0;
        __syncthreads();
        s[i] += t2;
        __syncthreads();
    }
    g_bsum[i] = s[i] - v;
}

__global__ void scan3_kernel() {
    int i = blockIdx.x * blockDim.x + threadIdx.x;
    if (i < N_NODES) {
        g_rowptr[i] += g_bsum[i >> 10];
        g_dinv[i] = rsqrtf((float)g_deg[i]);
    }
    if (i == 0) g_rowptr[N_NODES] = N_EDGES;
}

__global__ void fill_kernel(const int* __restrict__ src, const int* __restrict__ dst) {
    int e = blockIdx.x * blockDim.x + threadIdx.x;
    if (e < N_EDGES) {
        int s = clamp_node(src[e]);
        int d = clamp_node(dst[e]);
        int p = g_rowptr[d] + atomicAdd(&g_fill[d], 1);
        if (p >= 0 && p < N_EDGES) g_col[p] = s;
    }
}

// ---------------- propagation: warp per node; 30-edge batches, 5 independent gathers ----------------
template <bool FIRST, bool LAST>
__global__ void prop_kernel(float* __restrict__ out, const float* __restrict__ temp, int k) {
    const uint4* __restrict__ cur = (k & 1) ? g_nexth : g_curh;
    uint4* __restrict__ next = (k & 1) ? g_curh : g_nexth;
    const int warp = (blockIdx.x * blockDim.x + threadIdx.x) >> 5;
    const int lane = threadIdx.x & 31;
    if (warp >= N_NODES) return;
    const int i = warp;
    const int g = lane / 5;          // 0..5 edge group (lane 30,31 idle)
    const int sub = lane - g * 5;    // 0..4 chunk
    const bool grp = (lane < 30);
    const int start = g_rowptr[i], end = g_rowptr[i + 1];
    const float di = g_dinv[i];

    float c[8], acc[8];
#pragma unroll
    for (int j = 0; j < 8; j++) { c[j] = 0.f; acc[j] = 0.f; }
    if (lane < 5) {
        uint4 u = cur[(size_t)i * ROWC + lane];
        unpack8(u, c);
#pragma unroll
        for (int j = 0; j < 8; j++) acc[j] = c[j];   // self term s_i
    }

    const int gl = (g < 6) ? g : 0;
    const int subc = (sub < 5) ? sub : 0;
    int e0 = start;

    for (; e0 + 30 <= end; e0 += 30) {
        int col = 0;
        if (lane < 30) col = g_col[e0 + lane];
        int srcs[5];
#pragma unroll
        for (int it = 0; it < 5; it++)
            srcs[it] = __shfl_sync(0xFFFFFFFFu, col, it * 6 + gl);
        uint4 us[5];
#pragma unroll
        for (int it = 0; it < 5; it++)
            us[it] = cur[(size_t)srcs[it] * ROWC + subc];
#pragma unroll
        for (int it = 0; it < 5; it++) {
            float v[8];
            unpack8(us[it], v);
            if (grp) {
#pragma unroll
                for (int j = 0; j < 8; j++) acc[j] += v[j];
            }
        }
    }
    for (; e0 < end; e0 += 6) {
        int col = 0;
        if (lane < 6) {
            int li = e0 + lane;
            col = g_col[li < end ? li : end - 1];
        }
        int src = __shfl_sync(0xFFFFFFFFu, col, gl);
        float wv = (grp && (e0 + g < end)) ? 1.f : 0.f;
        uint4 u = cur[(size_t)src * ROWC + subc];
        float v[8];
        unpack8(u, v);
#pragma unroll
        for (int j = 0; j < 8; j++) acc[j] += wv * v[j];
    }

    // reduce 6 groups (stride-5 lanes) -> lanes 0..4
#pragma unroll
    for (int j = 0; j < 8; j++) {
        float v = acc[j];
        v += __shfl_down_sync(0xFFFFFFFFu, v, 15);
        float t1 = __shfl_down_sync(0xFFFFFFFFu, v, 5);
        float t2 = __shfl_down_sync(0xFFFFFFFFu, v, 10);
        acc[j] = v + t1 + t2;
    }

    const float tk = temp[k + 1];
    float h[8];
#pragma unroll
    for (int j = 0; j < 8; j++) h[j] = 0.f;
    if (lane < 5) {
#pragma unroll
        for (int j = 0; j < 8; j++) acc[j] *= di;         // nv = di * (sum + s_i)
        if (FIRST) {
            const float t0z = temp[0] / di;                // z = s / di
#pragma unroll
            for (int j = 0; j < 8; j++) h[j] = t0z * c[j] + tk * acc[j];
        } else {
            float4 a = g_hidden4[i * 10 + lane * 2];
            float4 b = g_hidden4[i * 10 + lane * 2 + 1];
            h[0] = a.x + tk * acc[0]; h[1] = a.y + tk * acc[1];
            h[2] = a.z + tk * acc[2]; h[3] = a.w + tk * acc[3];
            h[4] = b.x + tk * acc[4]; h[5] = b.y + tk * acc[5];
            h[6] = b.z + tk * acc[6]; h[7] = b.w + tk * acc[7];
        }
        if (!LAST) {
            float sc[8];
#pragma unroll
            for (int j = 0; j < 8; j++) sc[j] = di * acc[j];   // s' = di * nv
            next[(size_t)i * ROWC + lane] = pack8(sc);
            g_hidden4[i * 10 + lane * 2]     = make_float4(h[0], h[1], h[2], h[3]);
            g_hidden4[i * 10 + lane * 2 + 1] = make_float4(h[4], h[5], h[6], h[7]);
        }
    }
    if (LAST) {
        float m = -1e30f;
        if (lane < 5) {
#pragma unroll
            for (int j = 0; j < 8; j++) m = fmaxf(m, h[j]);
        }
#pragma unroll
        for (int o = 1; o < 8; o <<= 1) m = fmaxf(m, __shfl_xor_sync(0xFFFFFFFFu, m, o));
        float s = 0.f;
        if (lane < 5) {
#pragma unroll
            for (int j = 0; j < 8; j++) s += expf(h[j] - m);
        }
#pragma unroll
        for (int o = 1; o < 8; o <<= 1) s += __shfl_xor_sync(0xFFFFFFFFu, s, o);
        const float lse = m + logf(s);
        if (lane < 5) {
            float4* o4 = (float4*)(out + (size_t)i * OUT_CH + lane * 8);
            o4[0] = make_float4(h[0] - lse, h[1] - lse, h[2] - lse, h[3] - lse);
            o4[1] = make_float4(h[4] - lse, h[5] - lse, h[6] - lse, h[7] - lse);
        }
    }
}

// ---------------- launch: kernel launches ONLY ----------------
extern "C" void kernel_launch(void* const* d_in, const int* in_sizes, int n_in,
                              void* d_out, int out_size) {
    const float* x    = (const float*)d_in[0];
    const int*   ei   = (const int*)d_in[1];  // [2, N_EDGES] int32
    const float* W1   = (const float*)d_in[2];
    const float* b1   = (const float*)d_in[3];
    const float* W2   = (const float*)d_in[4];
    const float* b2   = (const float*)d_in[5];
    const float* gam  = (const float*)d_in[6];
    const float* bet  = (const float*)d_in[7];
    const float* mea  = (const float*)d_in[8];
    const float* var  = (const float*)d_in[9];
    const float* temp = (const float*)d_in[10];
    float* out = (float*)d_out;
    const int* srcp = ei;
    const int* dstp = ei + N_EDGES;

    // CSR first (stem needs g_dinv)
    zero_kernel<<<(N_NODES + 255) / 256, 256>>>();
    hist_kernel<<<(N_EDGES + 255) / 256, 256>>>(dstp);
    const int nb = (N_NODES + 1023) / 1024;  // 98
    scan1_kernel<<<nb, 1024>>>();
    scan2_kernel<<<1, 128>>>(nb);
    scan3_kernel<<<(N_NODES + 255) / 256, 256>>>();
    fill_kernel<<<(N_EDGES + 255) / 256, 256>>>(srcp, dstp);

    stem_kernel<<<(N_NODES + 127) / 128, 256>>>(x, W1, b1, W2, b2, gam, bet, mea, var);

    const int pgrid = (N_NODES * 32 + 255) / 256;
    prop_kernel<true, false><<<pgrid, 256>>>(nullptr, temp, 0);
    for (int k = 1; k < K_HOPS - 1; k++)
        prop_kernel<false, false><<<pgrid, 256>>>(nullptr, temp, k);
    prop_kernel<false, true><<<pgrid, 256>>>(out, temp, K_HOPS - 1);
}

// round 13
// speedup vs baseline: 1.5866x; 1.0298x over previous
#include <cuda_runtime.h>
#include <cuda_fp16.h>
#include <cstdint>

#define N_NODES 100000
#define N_EDGES 3200000
#define IN_CH   500
#define HID     64
#define OUT_CH  40
#define K_HOPS  10
#define ROWC    5    // 16B chunks per packed feature row (80B = 40 half)

// ---------------- scratch ----------------
__device__ int    g_deg[N_NODES];
__device__ int    g_fill[N_NODES];
__device__ int    g_rowptr[N_NODES + 1];
__device__ float  g_dinv[N_NODES];
__device__ int    g_col[N_EDGES];             // CSR col (src); weight folded into features
__device__ uint4  g_curh[N_NODES * ROWC];     // scaled fp16 features s = dinv*x (ping)
__device__ uint4  g_nexth[N_NODES * ROWC];    // (pong)
__device__ float4 g_hidden4[N_NODES * 10];    // fp32 hidden accumulator
__device__ int    g_bsum[128];

__device__ __forceinline__ int clamp_node(int v) {
    return v < 0 ? 0 : (v >= N_NODES ? N_NODES - 1 : v);
}

__device__ __forceinline__ void unpack8(uint4 u, float* f) {
    float2 a = __half22float2(*(__half2*)&u.x);
    float2 b = __half22float2(*(__half2*)&u.y);
    float2 c = __half22float2(*(__half2*)&u.z);
    float2 d = __half22float2(*(__half2*)&u.w);
    f[0] = a.x; f[1] = a.y; f[2] = b.x; f[3] = b.y;
    f[4] = c.x; f[5] = c.y; f[6] = d.x; f[7] = d.y;
}

__device__ __forceinline__ uint4 pack8(const float* f) {
    uint4 u;
    *(__half2*)&u.x = __floats2half2_rn(f[0], f[1]);
    *(__half2*)&u.y = __floats2half2_rn(f[2], f[3]);
    *(__half2*)&u.z = __floats2half2_rn(f[4], f[5]);
    *(__half2*)&u.w = __floats2half2_rn(f[6], f[7]);
    return u;
}

// ---------------- stem: BM=128, BN=64, BK=32; half2 HFMA2 inner loop ----------------
__global__ void stem_kernel(const float* __restrict__ x, const float* __restrict__ W1,
                            const float* __restrict__ b1, const float* __restrict__ W2,
                            const float* __restrict__ b2, const float* __restrict__ gamma,
                            const float* __restrict__ beta, const float* __restrict__ mean,
                            const float* __restrict__ var) {
    __shared__ float buf[10920];
    __shared__ float Ac[HID], Bc[HID], b2s[OUT_CH];
    __half2* As2 = (__half2*)buf;               // [128][17] = 2176 slots
    __half2* Bs2 = (__half2*)buf + 2176;        // [16][68]  = 1088 slots (aligned rows)
    float* hs  = buf;                           // [128][65] (phase 2)
    float* W2s = buf + 8320;                    // [40][65]

    const int t = threadIdx.x;        // 256 threads
    const int node0 = blockIdx.x * 128;
    const int tx = t & 15, ty = t >> 4;

    if (t < HID) {
        float A = gamma[t] * rsqrtf(var[t] + 1e-5f);
        Ac[t] = A;
        Bc[t] = (b1[t] - mean[t]) * A + beta[t];
    }
    if (t < OUT_CH) b2s[t] = b2[t];

    float acc[8][4];
#pragma unroll
    for (int r = 0; r < 8; r++)
#pragma unroll
        for (int c = 0; c < 4; c++) acc[r][c] = 0.f;

    const int arow = t >> 1;            // 0..127
    const int akp0 = (t & 1) * 8;       // half2-k offset 0 or 8
    const int bh = t & 63;              // hid
    const int bkp0 = (t >> 6) * 4;      // half2-k rows [bkp0, bkp0+4)

    for (int kk = 0; kk < IN_CH; kk += 32) {
        {
            int gn = node0 + arow;
            const float* xr = x + (size_t)gn * IN_CH + kk + akp0 * 2;
            __half2* dstA = As2 + arow * 17 + akp0;
#pragma unroll
            for (int j = 0; j < 8; j++) {
                int col = kk + (akp0 + j) * 2;
                float2 v = make_float2(0.f, 0.f);
                if (gn < N_NODES && col < IN_CH) v = *(const float2*)(xr + 2 * j);
                dstA[j] = __float22half2_rn(v);
            }
        }
        {
            const float* wr = W1 + (size_t)bh * IN_CH + kk + bkp0 * 2;
#pragma unroll
            for (int j = 0; j < 4; j++) {
                int col = kk + (bkp0 + j) * 2;
                float2 v = make_float2(0.f, 0.f);
                if (col < IN_CH) v = *(const float2*)(wr + 2 * j);
                Bs2[(bkp0 + j) * 68 + bh] = __float22half2_rn(v);
            }
        }
        __syncthreads();
        __half2 acc2[8][4];
#pragma unroll
        for (int r = 0; r < 8; r++)
#pragma unroll
            for (int c = 0; c < 4; c++) acc2[r][c] = __float2half2_rn(0.f);
#pragma unroll
        for (int kp = 0; kp < 16; kp++) {
            __half2 a2[8], b2v[4];
#pragma unroll
            for (int r = 0; r < 8; r++) a2[r] = As2[(ty * 8 + r) * 17 + kp];
#pragma unroll
            for (int c = 0; c < 4; c++) b2v[c] = Bs2[kp * 68 + tx * 4 + c];
#pragma unroll
            for (int r = 0; r < 8; r++)
#pragma unroll
                for (int c = 0; c < 4; c++) acc2[r][c] = __hfma2(a2[r], b2v[c], acc2[r][c]);
        }
#pragma unroll
        for (int r = 0; r < 8; r++)
#pragma unroll
            for (int c = 0; c < 4; c++) {
                float2 f = __half22float2(acc2[r][c]);
                acc[r][c] += f.x + f.y;
            }
        __syncthreads();
    }
#pragma unroll
    for (int r = 0; r < 8; r++)
#pragma unroll
        for (int c = 0; c < 4; c++) {
            int hd = tx * 4 + c;
            float v = acc[r][c] * Ac[hd] + Bc[hd];
            hs[(ty * 8 + r) * 65 + hd] = fmaxf(v, 0.f);
        }
    for (int idx = t; idx < OUT_CH * HID; idx += 256)
        W2s[(idx >> 6) * 65 + (idx & 63)] = W2[idx];
    __syncthreads();

    const int n = t >> 1, ob = (t & 1) * 20;
    float outv[20];
#pragma unroll
    for (int j = 0; j < 20; j++) outv[j] = b2s[ob + j];
#pragma unroll 8
    for (int c = 0; c < HID; c++) {
        float hv = hs[n * 65 + c];
#pragma unroll
        for (int j = 0; j < 20; j++) outv[j] += hv * W2s[(ob + j) * 65 + c];
    }
    int gn = node0 + n;
    if (gn < N_NODES) {
        const float di = g_dinv[gn];
        __half2* dst = (__half2*)g_curh;   // packed: 20 half2 per node
#pragma unroll
        for (int j = 0; j < 10; j++)
            dst[(size_t)gn * 20 + ob / 2 + j] =
                __floats2half2_rn(di * outv[2 * j], di * outv[2 * j + 1]);
    }
}

// ---------------- CSR build ----------------
__global__ void zero_kernel() {
    int i = blockIdx.x * blockDim.x + threadIdx.x;
    if (i < N_NODES) { g_deg[i] = 1; g_fill[i] = 0; }  // 1 = self loop
}

__global__ void hist_kernel(const int* __restrict__ dst) {
    int e = blockIdx.x * blockDim.x + threadIdx.x;
    if (e < N_EDGES) atomicAdd(&g_deg[clamp_node(dst[e])], 1);
}

__device__ __forceinline__ int block_incl_scan(int v, int* warpSums) {
    int lane = threadIdx.x & 31, wid = threadIdx.x >> 5;
#pragma unroll
    for (int o = 1; o < 32; o <<= 1) {
        int nv = __shfl_up_sync(0xFFFFFFFFu, v, o);
        if (lane >= o) v += nv;
    }
    if (lane == 31) warpSums[wid] = v;
    __syncthreads();
    if (wid == 0) {
        int s = (lane < (int)(blockDim.x >> 5)) ? warpSums[lane] : 0;
#pragma unroll
        for (int o = 1; o < 32; o <<= 1) {
            int nv = __shfl_up_sync(0xFFFFFFFFu, s, o);
            if (lane >= o) s += nv;
        }
        warpSums[lane] = s;
    }
    __syncthreads();
    if (wid > 0) v += warpSums[wid - 1];
    return v;
}

__global__ void scan1_kernel() {
    __shared__ int ws[32];
    int i = blockIdx.x * 1024 + threadIdx.x;
    int v = (i < N_NODES) ? (g_deg[i] - 1) : 0;
    int incl = block_incl_scan(v, ws);
    if (i < N_NODES) g_rowptr[i] = incl - v;
    if (threadIdx.x == 1023) g_bsum[blockIdx.x] = incl;
}

__global__ void scan2_kernel(int nb) {
    __shared__ int s[128];
    int i = threadIdx.x;
    int v = (i < nb) ? g_bsum[i] : 0;
    s[i] = v;
    __syncthreads();
    for (int o = 1; o < 128; o <<= 1) {
        int t2 = (i >= o) ? s[i - o] : 0;
        __syncthreads();
        s[i] += t2;
        __syncthreads();
    }
    g_bsum[i] = s[i] - v;
}

__global__ void scan3_kernel() {
    int i = blockIdx.x * blockDim.x + threadIdx.x;
    if (i < N_NODES) {
        g_rowptr[i] += g_bsum[i >> 10];
        g_dinv[i] = rsqrtf((float)g_deg[i]);
    }
    if (i == 0) g_rowptr[N_NODES] = N_EDGES;
}

__global__ void fill_kernel(const int* __restrict__ src, const int* __restrict__ dst) {
    int e = blockIdx.x * blockDim.x + threadIdx.x;
    if (e < N_EDGES) {
        int s = clamp_node(src[e]);
        int d = clamp_node(dst[e]);
        int p = g_rowptr[d] + atomicAdd(&g_fill[d], 1);
        if (p >= 0 && p < N_EDGES) g_col[p] = s;
    }
}

// ---------------- propagation: warp per node; 64-thread blocks for fast slot recycling ----------------
template <bool FIRST, bool LAST>
__global__ void prop_kernel(float* __restrict__ out, const float* __restrict__ temp, int k) {
    const uint4* __restrict__ cur = (k & 1) ? g_nexth : g_curh;
    uint4* __restrict__ next = (k & 1) ? g_curh : g_nexth;
    const int warp = (blockIdx.x * blockDim.x + threadIdx.x) >> 5;
    const int lane = threadIdx.x & 31;
    if (warp >= N_NODES) return;
    const int i = warp;
    const int g = lane / 5;          // 0..5 edge group (lane 30,31 idle)
    const int sub = lane - g * 5;    // 0..4 chunk
    const bool grp = (lane < 30);
    const int start = g_rowptr[i], end = g_rowptr[i + 1];
    const float di = g_dinv[i];

    float c[8], acc[8];
#pragma unroll
    for (int j = 0; j < 8; j++) { c[j] = 0.f; acc[j] = 0.f; }
    if (lane < 5) {
        uint4 u = cur[(size_t)i * ROWC + lane];
        unpack8(u, c);
#pragma unroll
        for (int j = 0; j < 8; j++) acc[j] = c[j];   // self term s_i
    }

    const int gl = (g < 6) ? g : 0;
    const int subc = (sub < 5) ? sub : 0;
    int e0 = start;

    for (; e0 + 30 <= end; e0 += 30) {
        int col = 0;
        if (lane < 30) col = g_col[e0 + lane];
        int srcs[5];
#pragma unroll
        for (int it = 0; it < 5; it++)
            srcs[it] = __shfl_sync(0xFFFFFFFFu, col, it * 6 + gl);
        uint4 us[5];
#pragma unroll
        for (int it = 0; it < 5; it++)
            us[it] = cur[(size_t)srcs[it] * ROWC + subc];
#pragma unroll
        for (int it = 0; it < 5; it++) {
            float v[8];
            unpack8(us[it], v);
            if (grp) {
#pragma unroll
                for (int j = 0; j < 8; j++) acc[j] += v[j];
            }
        }
    }
    for (; e0 < end; e0 += 6) {
        int col = 0;
        if (lane < 6) {
            int li = e0 + lane;
            col = g_col[li < end ? li : end - 1];
        }
        int src = __shfl_sync(0xFFFFFFFFu, col, gl);
        float wv = (grp && (e0 + g < end)) ? 1.f : 0.f;
        uint4 u = cur[(size_t)src * ROWC + subc];
        float v[8];
        unpack8(u, v);
#pragma unroll
        for (int j = 0; j < 8; j++) acc[j] += wv * v[j];
    }

    // reduce 6 groups (stride-5 lanes) -> lanes 0..4
#pragma unroll
    for (int j = 0; j < 8; j++) {
        float v = acc[j];
        v += __shfl_down_sync(0xFFFFFFFFu, v, 15);
        float t1 = __shfl_down_sync(0xFFFFFFFFu, v, 5);
        float t2 = __shfl_down_sync(0xFFFFFFFFu, v, 10);
        acc[j] = v + t1 + t2;
    }

    const float tk = temp[k + 1];
    float h[8];
#pragma unroll
    for (int j = 0; j < 8; j++) h[j] = 0.f;
    if (lane < 5) {
#pragma unroll
        for (int j = 0; j < 8; j++) acc[j] *= di;         // nv = di * (sum + s_i)
        if (FIRST) {
            const float t0z = temp[0] / di;                // z = s / di
#pragma unroll
            for (int j = 0; j < 8; j++) h[j] = t0z * c[j] + tk * acc[j];
        } else {
            float4 a = g_hidden4[i * 10 + lane * 2];
            float4 b = g_hidden4[i * 10 + lane * 2 + 1];
            h[0] = a.x + tk * acc[0]; h[1] = a.y + tk * acc[1];
            h[2] = a.z + tk * acc[2]; h[3] = a.w + tk * acc[3];
            h[4] = b.x + tk * acc[4]; h[5] = b.y + tk * acc[5];
            h[6] = b.z + tk * acc[6]; h[7] = b.w + tk * acc[7];
        }
        if (!LAST) {
            float sc[8];
#pragma unroll
            for (int j = 0; j < 8; j++) sc[j] = di * acc[j];   // s' = di * nv
            next[(size_t)i * ROWC + lane] = pack8(sc);
            g_hidden4[i * 10 + lane * 2]     = make_float4(h[0], h[1], h[2], h[3]);
            g_hidden4[i * 10 + lane * 2 + 1] = make_float4(h[4], h[5], h[6], h[7]);
        }
    }
    if (LAST) {
        float m = -1e30f;
        if (lane < 5) {
#pragma unroll
            for (int j = 0; j < 8; j++) m = fmaxf(m, h[j]);
        }
#pragma unroll
        for (int o = 1; o < 8; o <<= 1) m = fmaxf(m, __shfl_xor_sync(0xFFFFFFFFu, m, o));
        float s = 0.f;
        if (lane < 5) {
#pragma unroll
            for (int j = 0; j < 8; j++) s += expf(h[j] - m);
        }
#pragma unroll
        for (int o = 1; o < 8; o <<= 1) s += __shfl_xor_sync(0xFFFFFFFFu, s, o);
        const float lse = m + logf(s);
        if (lane < 5) {
            float4* o4 = (float4*)(out + (size_t)i * OUT_CH + lane * 8);
            o4[0] = make_float4(h[0] - lse, h[1] - lse, h[2] - lse, h[3] - lse);
            o4[1] = make_float4(h[4] - lse, h[5] - lse, h[6] - lse, h[7] - lse);
        }
    }
}

// ---------------- launch: kernel launches ONLY ----------------
extern "C" void kernel_launch(void* const* d_in, const int* in_sizes, int n_in,
                              void* d_out, int out_size) {
    const float* x    = (const float*)d_in[0];
    const int*   ei   = (const int*)d_in[1];  // [2, N_EDGES] int32
    const float* W1   = (const float*)d_in[2];
    const float* b1   = (const float*)d_in[3];
    const float* W2   = (const float*)d_in[4];
    const float* b2   = (const float*)d_in[5];
    const float* gam  = (const float*)d_in[6];
    const float* bet  = (const float*)d_in[7];
    const float* mea  = (const float*)d_in[8];
    const float* var  = (const float*)d_in[9];
    const float* temp = (const float*)d_in[10];
    float* out = (float*)d_out;
    const int* srcp = ei;
    const int* dstp = ei + N_EDGES;

    // CSR first (stem needs g_dinv)
    zero_kernel<<<(N_NODES + 255) / 256, 256>>>();
    hist_kernel<<<(N_EDGES + 255) / 256, 256>>>(dstp);
    const int nb = (N_NODES + 1023) / 1024;  // 98
    scan1_kernel<<<nb, 1024>>>();
    scan2_kernel<<<1, 128>>>(nb);
    scan3_kernel<<<(N_NODES + 255) / 256, 256>>>();
    fill_kernel<<<(N_EDGES + 255) / 256, 256>>>(srcp, dstp);

    stem_kernel<<<(N_NODES + 127) / 128, 256>>>(x, W1, b1, W2, b2, gam, bet, mea, var);

    // 64-thread blocks: 2 warps/block -> block slots recycle on max-of-2, not max-of-8
    const int pgrid = (N_NODES * 32 + 63) / 64;
    prop_kernel<true, false><<<pgrid, 64>>>(nullptr, temp, 0);
    for (int k = 1; k < K_HOPS - 1; k++)
        prop_kernel<false, false><<<pgrid, 64>>>(nullptr, temp, k);
    prop_kernel<false, true><<<pgrid, 64>>>(out, temp, K_HOPS - 1);
}

// round 14
// speedup vs baseline: 1.6374x; 1.0320x over previous
#include <cuda_runtime.h>
#include <cuda_fp16.h>
#include <cstdint>

#define N_NODES 100000
#define N_EDGES 3200000
#define IN_CH   500
#define HID     64
#define OUT_CH  40
#define K_HOPS  10
#define ROWC    5    // 16B chunks per packed feature row (80B = 40 half)

// ---------------- scratch ----------------
__device__ int    g_deg[N_NODES];
__device__ int    g_fill[N_NODES];
__device__ int    g_rowptr[N_NODES + 1];
__device__ float  g_dinv[N_NODES];
__device__ int    g_col[N_EDGES];             // CSR col (src); weight folded into features
__device__ uint4  g_curh[N_NODES * ROWC];     // scaled fp16 features s = dinv*x (ping)
__device__ uint4  g_nexth[N_NODES * ROWC];    // (pong)
__device__ float4 g_hidden4[N_NODES * 10];    // fp32 hidden accumulator
__device__ int    g_bsum[128];

__device__ __forceinline__ int clamp_node(int v) {
    return v < 0 ? 0 : (v >= N_NODES ? N_NODES - 1 : v);
}

__device__ __forceinline__ void unpack8(uint4 u, float* f) {
    float2 a = __half22float2(*(__half2*)&u.x);
    float2 b = __half22float2(*(__half2*)&u.y);
    float2 c = __half22float2(*(__half2*)&u.z);
    float2 d = __half22float2(*(__half2*)&u.w);
    f[0] = a.x; f[1] = a.y; f[2] = b.x; f[3] = b.y;
    f[4] = c.x; f[5] = c.y; f[6] = d.x; f[7] = d.y;
}

__device__ __forceinline__ uint4 pack8(const float* f) {
    uint4 u;
    *(__half2*)&u.x = __floats2half2_rn(f[0], f[1]);
    *(__half2*)&u.y = __floats2half2_rn(f[2], f[3]);
    *(__half2*)&u.z = __floats2half2_rn(f[4], f[5]);
    *(__half2*)&u.w = __floats2half2_rn(f[6], f[7]);
    return u;
}

__device__ __forceinline__ void mma16816(float& c0, float& c1, float& c2, float& c3,
                                         uint32_t a0, uint32_t a1, uint32_t a2, uint32_t a3,
                                         uint32_t b0, uint32_t b1) {
    asm volatile(
        "mma.sync.aligned.m16n8k16.row.col.f32.f16.f16.f32 "
        "{%0,%1,%2,%3}, {%4,%5,%6,%7}, {%8,%9}, {%0,%1,%2,%3};"
        : "+f"(c0), "+f"(c1), "+f"(c2), "+f"(c3)
        : "r"(a0), "r"(a1), "r"(a2), "r"(a3), "r"(b0), "r"(b1));
}

// ---------------- stem: BM=128, BK=32; HMMA m16n8k16, fp32 accumulators ----------------
// phase1 smem (half2): As2[128][17] row-major + Bs2[64][17] n-major (rows of W1)
// phase2 (fp32): hs[128][65] + W2s[40][65]
__global__ void stem_kernel(const float* __restrict__ x, const float* __restrict__ W1,
                            const float* __restrict__ b1, const float* __restrict__ W2,
                            const float* __restrict__ b2, const float* __restrict__ gamma,
                            const float* __restrict__ beta, const float* __restrict__ mean,
                            const float* __restrict__ var) {
    __shared__ float buf[10920];
    __shared__ float Ac[HID], Bc[HID], b2s[OUT_CH];
    __half2* As2 = (__half2*)buf;               // [128][17] = 2176 slots
    __half2* Bs2 = (__half2*)buf + 2176;        // [64][17]  = 1088 slots
    float* hs  = buf;                           // [128][65] (phase 2)
    float* W2s = buf + 8320;                    // [40][65]

    const int t = threadIdx.x;        // 256 threads = 8 warps
    const int node0 = blockIdx.x * 128;
    const int wid = t >> 5, lane = t & 31;
    const int g = lane >> 2, tg = lane & 3;     // mma groupID / thread-in-group

    if (t < HID) {
        float A = gamma[t] * rsqrtf(var[t] + 1e-5f);
        Ac[t] = A;
        Bc[t] = (b1[t] - mean[t]) * A + beta[t];
    }
    if (t < OUT_CH) b2s[t] = b2[t];

    float c[8][4];                    // 8 n-tiles x (c0..c3), fp32
#pragma unroll
    for (int nt = 0; nt < 8; nt++)
#pragma unroll
        for (int q = 0; q < 4; q++) c[nt][q] = 0.f;

    const int arow = t >> 1;            // 0..127
    const int akp0 = (t & 1) * 8;       // half2-k offset 0 or 8
    const int bh = t & 63;              // W1 row (hid n)
    const int bkp0 = (t >> 6) * 4;      // half2-k cols [bkp0, bkp0+4)

    for (int kk = 0; kk < IN_CH; kk += 32) {
        // load As2: thread -> row arow, half2 cols [akp0, akp0+8)  (proven loader)
        {
            int gn = node0 + arow;
            const float* xr = x + (size_t)gn * IN_CH + kk + akp0 * 2;
            __half2* dstA = As2 + arow * 17 + akp0;
#pragma unroll
            for (int j = 0; j < 8; j++) {
                int col = kk + (akp0 + j) * 2;
                float2 v = make_float2(0.f, 0.f);
                if (gn < N_NODES && col < IN_CH) v = *(const float2*)(xr + 2 * j);
                dstA[j] = __float22half2_rn(v);
            }
        }
        // load Bs2 n-major: thread -> hid bh, half2-k [bkp0, bkp0+4) straight from W1 row
        {
            const float* wr = W1 + (size_t)bh * IN_CH + kk + bkp0 * 2;
#pragma unroll
            for (int j = 0; j < 4; j++) {
                int col = kk + (bkp0 + j) * 2;
                float2 v = make_float2(0.f, 0.f);
                if (col < IN_CH) v = *(const float2*)(wr + 2 * j);
                Bs2[bh * 17 + bkp0 + j] = __float22half2_rn(v);
            }
        }
        __syncthreads();
        // warp computes rows [wid*16, wid*16+16) x all 64 hid; 2 k-steps of 16
        const int r0 = wid * 16 + g;
#pragma unroll
        for (int ks = 0; ks < 2; ks++) {
            uint32_t A0 = *(const uint32_t*)&As2[r0 * 17 + ks * 8 + tg];
            uint32_t A1 = *(const uint32_t*)&As2[(r0 + 8) * 17 + ks * 8 + tg];
            uint32_t A2 = *(const uint32_t*)&As2[r0 * 17 + ks * 8 + tg + 4];
            uint32_t A3 = *(const uint32_t*)&As2[(r0 + 8) * 17 + ks * 8 + tg + 4];
#pragma unroll
            for (int nt = 0; nt < 8; nt++) {
                uint32_t B0 = *(const uint32_t*)&Bs2[(nt * 8 + g) * 17 + ks * 8 + tg];
                uint32_t B1 = *(const uint32_t*)&Bs2[(nt * 8 + g) * 17 + ks * 8 + tg + 4];
                mma16816(c[nt][0], c[nt][1], c[nt][2], c[nt][3], A0, A1, A2, A3, B0, B1);
            }
        }
        __syncthreads();
    }
    // BN + relu -> hs.  C layout: c0,c1 -> row g, cols tg*2,+1; c2,c3 -> row g+8
    {
        const int row0 = wid * 16 + g;
#pragma unroll
        for (int nt = 0; nt < 8; nt++) {
            int col0 = nt * 8 + tg * 2;
            hs[row0 * 65 + col0]       = fmaxf(c[nt][0] * Ac[col0] + Bc[col0], 0.f);
            hs[row0 * 65 + col0 + 1]   = fmaxf(c[nt][1] * Ac[col0 + 1] + Bc[col0 + 1], 0.f);
            hs[(row0 + 8) * 65 + col0]     = fmaxf(c[nt][2] * Ac[col0] + Bc[col0], 0.f);
            hs[(row0 + 8) * 65 + col0 + 1] = fmaxf(c[nt][3] * Ac[col0 + 1] + Bc[col0 + 1], 0.f);
        }
    }
    for (int idx = t; idx < OUT_CH * HID; idx += 256)
        W2s[(idx >> 6) * 65 + (idx & 63)] = W2[idx];
    __syncthreads();

    // phase 2: z = hs @ W2^T (fp32)
    const int n = t >> 1, ob = (t & 1) * 20;
    float outv[20];
#pragma unroll
    for (int j = 0; j < 20; j++) outv[j] = b2s[ob + j];
#pragma unroll 8
    for (int cc = 0; cc < HID; cc++) {
        float hv = hs[n * 65 + cc];
#pragma unroll
        for (int j = 0; j < 20; j++) outv[j] += hv * W2s[(ob + j) * 65 + cc];
    }
    int gn = node0 + n;
    if (gn < N_NODES) {
        const float di = g_dinv[gn];
        __half2* dst = (__half2*)g_curh;   // packed: 20 half2 per node
#pragma unroll
        for (int j = 0; j < 10; j++)
            dst[(size_t)gn * 20 + ob / 2 + j] =
                __floats2half2_rn(di * outv[2 * j], di * outv[2 * j + 1]);
    }
}

// ---------------- CSR build ----------------
__global__ void zero_kernel() {
    int i = blockIdx.x * blockDim.x + threadIdx.x;
    if (i < N_NODES) { g_deg[i] = 1; g_fill[i] = 0; }  // 1 = self loop
}

__global__ void hist_kernel(const int* __restrict__ dst) {
    int e = blockIdx.x * blockDim.x + threadIdx.x;
    if (e < N_EDGES) atomicAdd(&g_deg[clamp_node(dst[e])], 1);
}

__device__ __forceinline__ int block_incl_scan(int v, int* warpSums) {
    int lane = threadIdx.x & 31, wid = threadIdx.x >> 5;
#pragma unroll
    for (int o = 1; o < 32; o <<= 1) {
        int nv = __shfl_up_sync(0xFFFFFFFFu, v, o);
        if (lane >= o) v += nv;
    }
    if (lane == 31) warpSums[wid] = v;
    __syncthreads();
    if (wid == 0) {
        int s = (lane < (int)(blockDim.x >> 5)) ? warpSums[lane] : 0;
#pragma unroll
        for (int o = 1; o < 32; o <<= 1) {
            int nv = __shfl_up_sync(0xFFFFFFFFu, s, o);
            if (lane >= o) s += nv;
        }
        warpSums[lane] = s;
    }
    __syncthreads();
    if (wid > 0) v += warpSums[wid - 1];
    return v;
}

__global__ void scan1_kernel() {
    __shared__ int ws[32];
    int i = blockIdx.x * 1024 + threadIdx.x;
    int v = (i < N_NODES) ? (g_deg[i] - 1) : 0;
    int incl = block_incl_scan(v, ws);
    if (i < N_NODES) g_rowptr[i] = incl - v;
    if (threadIdx.x == 1023) g_bsum[blockIdx.x] = incl;
}

__global__ void scan2_kernel(int nb) {
    __shared__ int s[128];
    int i = threadIdx.x;
    int v = (i < nb) ? g_bsum[i] : 0;
    s[i] = v;
    __syncthreads();
    for (int o = 1; o < 128; o <<= 1) {
        int t2 = (i >= o) ? s[i - o] : 0;
        __syncthreads();
        s[i] += t2;
        __syncthreads();
    }
    g_bsum[i] = s[i] - v;
}

__global__ void scan3_kernel() {
    int i = blockIdx.x * blockDim.x + threadIdx.x;
    if (i < N_NODES) {
        g_rowptr[i] += g_bsum[i >> 10];
        g_dinv[i] = rsqrtf((float)g_deg[i]);
    }
    if (i == 0) g_rowptr[N_NODES] = N_EDGES;
}

__global__ void fill_kernel(const int* __restrict__ src, const int* __restrict__ dst) {
    int e = blockIdx.x * blockDim.x + threadIdx.x;
    if (e < N_EDGES) {
        int s = clamp_node(src[e]);
        int d = clamp_node(dst[e]);
        int p = g_rowptr[d] + atomicAdd(&g_fill[d], 1);
        if (p >= 0 && p < N_EDGES) g_col[p] = s;
    }
}

// ---------------- propagation: warp per node; 64-thread blocks; 30-edge batches ----------------
template <bool FIRST, bool LAST>
__global__ void prop_kernel(float* __restrict__ out, const float* __restrict__ temp, int k) {
    const uint4* __restrict__ cur = (k & 1) ? g_nexth : g_curh;
    uint4* __restrict__ next = (k & 1) ? g_curh : g_nexth;
    const int warp = (blockIdx.x * blockDim.x + threadIdx.x) >> 5;
    const int lane = threadIdx.x & 31;
    if (warp >= N_NODES) return;
    const int i = warp;
    const int g = lane / 5;          // 0..5 edge group (lane 30,31 idle)
    const int sub = lane - g * 5;    // 0..4 chunk
    const bool grp = (lane < 30);
    const int start = g_rowptr[i], end = g_rowptr[i + 1];
    const float di = g_dinv[i];

    float c[8], acc[8];
#pragma unroll
    for (int j = 0; j < 8; j++) { c[j] = 0.f; acc[j] = 0.f; }
    if (lane < 5) {
        uint4 u = cur[(size_t)i * ROWC + lane];
        unpack8(u, c);
#pragma unroll
        for (int j = 0; j < 8; j++) acc[j] = c[j];   // self term s_i
    }

    const int gl = (g < 6) ? g : 0;
    const int subc = (sub < 5) ? sub : 0;
    int e0 = start;

    for (; e0 + 30 <= end; e0 += 30) {
        int col = 0;
        if (lane < 30) col = g_col[e0 + lane];
        int srcs[5];
#pragma unroll
        for (int it = 0; it < 5; it++)
            srcs[it] = __shfl_sync(0xFFFFFFFFu, col, it * 6 + gl);
        uint4 us[5];
#pragma unroll
        for (int it = 0; it < 5; it++)
            us[it] = cur[(size_t)srcs[it] * ROWC + subc];
#pragma unroll
        for (int it = 0; it < 5; it++) {
            float v[8];
            unpack8(us[it], v);
            if (grp) {
#pragma unroll
                for (int j = 0; j < 8; j++) acc[j] += v[j];
            }
        }
    }
    for (; e0 < end; e0 += 6) {
        int col = 0;
        if (lane < 6) {
            int li = e0 + lane;
            col = g_col[li < end ? li : end - 1];
        }
        int src = __shfl_sync(0xFFFFFFFFu, col, gl);
        float wv = (grp && (e0 + g < end)) ? 1.f : 0.f;
        uint4 u = cur[(size_t)src * ROWC + subc];
        float v[8];
        unpack8(u, v);
#pragma unroll
        for (int j = 0; j < 8; j++) acc[j] += wv * v[j];
    }

    // reduce 6 groups (stride-5 lanes) -> lanes 0..4
#pragma unroll
    for (int j = 0; j < 8; j++) {
        float v = acc[j];
        v += __shfl_down_sync(0xFFFFFFFFu, v, 15);
        float t1 = __shfl_down_sync(0xFFFFFFFFu, v, 5);
        float t2 = __shfl_down_sync(0xFFFFFFFFu, v, 10);
        acc[j] = v + t1 + t2;
    }

    const float tk = temp[k + 1];
    float h[8];
#pragma unroll
    for (int j = 0; j < 8; j++) h[j] = 0.f;
    if (lane < 5) {
#pragma unroll
        for (int j = 0; j < 8; j++) acc[j] *= di;         // nv = di * (sum + s_i)
        if (FIRST) {
            const float t0z = temp[0] / di;                // z = s / di
#pragma unroll
            for (int j = 0; j < 8; j++) h[j] = t0z * c[j] + tk * acc[j];
        } else {
            float4 a = g_hidden4[i * 10 + lane * 2];
            float4 b = g_hidden4[i * 10 + lane * 2 + 1];
            h[0] = a.x + tk * acc[0]; h[1] = a.y + tk * acc[1];
            h[2] = a.z + tk * acc[2]; h[3] = a.w + tk * acc[3];
            h[4] = b.x + tk * acc[4]; h[5] = b.y + tk * acc[5];
            h[6] = b.z + tk * acc[6]; h[7] = b.w + tk * acc[7];
        }
        if (!LAST) {
            float sc[8];
#pragma unroll
            for (int j = 0; j < 8; j++) sc[j] = di * acc[j];   // s' = di * nv
            next[(size_t)i * ROWC + lane] = pack8(sc);
            g_hidden4[i * 10 + lane * 2]     = make_float4(h[0], h[1], h[2], h[3]);
            g_hidden4[i * 10 + lane * 2 + 1] = make_float4(h[4], h[5], h[6], h[7]);
        }
    }
    if (LAST) {
        float m = -1e30f;
        if (lane < 5) {
#pragma unroll
            for (int j = 0; j < 8; j++) m = fmaxf(m, h[j]);
        }
#pragma unroll
        for (int o = 1; o < 8; o <<= 1) m = fmaxf(m, __shfl_xor_sync(0xFFFFFFFFu, m, o));
        float s = 0.f;
        if (lane < 5) {
#pragma unroll
            for (int j = 0; j < 8; j++) s += expf(h[j] - m);
        }
#pragma unroll
        for (int o = 1; o < 8; o <<= 1) s += __shfl_xor_sync(0xFFFFFFFFu, s, o);
        const float lse = m + logf(s);
        if (lane < 5) {
            float4* o4 = (float4*)(out + (size_t)i * OUT_CH + lane * 8);
            o4[0] = make_float4(h[0] - lse, h[1] - lse, h[2] - lse, h[3] - lse);
            o4[1] = make_float4(h[4] - lse, h[5] - lse, h[6] - lse, h[7] - lse);
        }
    }
}

// ---------------- launch: kernel launches ONLY ----------------
extern "C" void kernel_launch(void* const* d_in, const int* in_sizes, int n_in,
                              void* d_out, int out_size) {
    const float* x    = (const float*)d_in[0];
    const int*   ei   = (const int*)d_in[1];  // [2, N_EDGES] int32
    const float* W1   = (const float*)d_in[2];
    const float* b1   = (const float*)d_in[3];
    const float* W2   = (const float*)d_in[4];
    const float* b2   = (const float*)d_in[5];
    const float* gam  = (const float*)d_in[6];
    const float* bet  = (const float*)d_in[7];
    const float* mea  = (const float*)d_in[8];
    const float* var  = (const float*)d_in[9];
    const float* temp = (const float*)d_in[10];
    float* out = (float*)d_out;
    const int* srcp = ei;
    const int* dstp = ei + N_EDGES;

    // CSR first (stem needs g_dinv)
    zero_kernel<<<(N_NODES + 255) / 256, 256>>>();
    hist_kernel<<<(N_EDGES + 255) / 256, 256>>>(dstp);
    const int nb = (N_NODES + 1023) / 1024;  // 98
    scan1_kernel<<<nb, 1024>>>();
    scan2_kernel<<<1, 128>>>(nb);
    scan3_kernel<<<(N_NODES + 255) / 256, 256>>>();
    fill_kernel<<<(N_EDGES + 255) / 256, 256>>>(srcp, dstp);

    stem_kernel<<<(N_NODES + 127) / 128, 256>>>(x, W1, b1, W2, b2, gam, bet, mea, var);

    const int pgrid = (N_NODES * 32 + 63) / 64;
    prop_kernel<true, false><<<pgrid, 64>>>(nullptr, temp, 0);
    for (int k = 1; k < K_HOPS - 1; k++)
        prop_kernel<false, false><<<pgrid, 64>>>(nullptr, temp, k);
    prop_kernel<false, true><<<pgrid, 64>>>(out, temp, K_HOPS - 1);
}

// round 15
// speedup vs baseline: 1.6380x; 1.0004x over previous
#include <cuda_runtime.h>
#include <cuda_fp16.h>
#include <cstdint>

#define N_NODES 100000
#define N_EDGES 3200000
#define IN_CH   500
#define HID     64
#define OUT_CH  40
#define K_HOPS  10
#define RS      8    // uint4 per feature row: 128B padded (5 chunks used)

// ---------------- scratch ----------------
__device__ int    g_deg[N_NODES];
__device__ int    g_fill[N_NODES];
__device__ int    g_rowptr[N_NODES + 1];
__device__ float  g_dinv[N_NODES];
__device__ int    g_col[N_EDGES];             // CSR col (src); weight folded into features
__device__ uint4  g_curh[N_NODES * RS];       // scaled fp16 features, 128B/row (ping)
__device__ uint4  g_nexth[N_NODES * RS];      // (pong)
__device__ float4 g_hidden4[N_NODES * 10];    // fp32 hidden accumulator
__device__ int    g_bsum[128];

__device__ __forceinline__ int clamp_node(int v) {
    return v < 0 ? 0 : (v >= N_NODES ? N_NODES - 1 : v);
}

__device__ __forceinline__ void unpack8(uint4 u, float* f) {
    float2 a = __half22float2(*(__half2*)&u.x);
    float2 b = __half22float2(*(__half2*)&u.y);
    float2 c = __half22float2(*(__half2*)&u.z);
    float2 d = __half22float2(*(__half2*)&u.w);
    f[0] = a.x; f[1] = a.y; f[2] = b.x; f[3] = b.y;
    f[4] = c.x; f[5] = c.y; f[6] = d.x; f[7] = d.y;
}

__device__ __forceinline__ uint4 pack8(const float* f) {
    uint4 u;
    *(__half2*)&u.x = __floats2half2_rn(f[0], f[1]);
    *(__half2*)&u.y = __floats2half2_rn(f[2], f[3]);
    *(__half2*)&u.z = __floats2half2_rn(f[4], f[5]);
    *(__half2*)&u.w = __floats2half2_rn(f[6], f[7]);
    return u;
}

__device__ __forceinline__ void mma16816(float& c0, float& c1, float& c2, float& c3,
                                         uint32_t a0, uint32_t a1, uint32_t a2, uint32_t a3,
                                         uint32_t b0, uint32_t b1) {
    asm volatile(
        "mma.sync.aligned.m16n8k16.row.col.f32.f16.f16.f32 "
        "{%0,%1,%2,%3}, {%4,%5,%6,%7}, {%8,%9}, {%0,%1,%2,%3};"
        : "+f"(c0), "+f"(c1), "+f"(c2), "+f"(c3)
        : "r"(a0), "r"(a1), "r"(a2), "r"(a3), "r"(b0), "r"(b1));
}

// ---------------- stem: BM=128, BK=32; HMMA m16n8k16, fp32 accumulators ----------------
__global__ void stem_kernel(const float* __restrict__ x, const float* __restrict__ W1,
                            const float* __restrict__ b1, const float* __restrict__ W2,
                            const float* __restrict__ b2, const float* __restrict__ gamma,
                            const float* __restrict__ beta, const float* __restrict__ mean,
                            const float* __restrict__ var) {
    __shared__ float buf[10920];
    __shared__ float Ac[HID], Bc[HID], b2s[OUT_CH];
    __half2* As2 = (__half2*)buf;               // [128][17] = 2176 slots
    __half2* Bs2 = (__half2*)buf + 2176;        // [64][17]  = 1088 slots
    float* hs  = buf;                           // [128][65] (phase 2)
    float* W2s = buf + 8320;                    // [40][65]

    const int t = threadIdx.x;        // 256 threads = 8 warps
    const int node0 = blockIdx.x * 128;
    const int wid = t >> 5, lane = t & 31;
    const int g = lane >> 2, tg = lane & 3;

    if (t < HID) {
        float A = gamma[t] * rsqrtf(var[t] + 1e-5f);
        Ac[t] = A;
        Bc[t] = (b1[t] - mean[t]) * A + beta[t];
    }
    if (t < OUT_CH) b2s[t] = b2[t];

    float c[8][4];
#pragma unroll
    for (int nt = 0; nt < 8; nt++)
#pragma unroll
        for (int q = 0; q < 4; q++) c[nt][q] = 0.f;

    const int arow = t >> 1;
    const int akp0 = (t & 1) * 8;
    const int bh = t & 63;
    const int bkp0 = (t >> 6) * 4;

    for (int kk = 0; kk < IN_CH; kk += 32) {
        {
            int gn = node0 + arow;
            const float* xr = x + (size_t)gn * IN_CH + kk + akp0 * 2;
            __half2* dstA = As2 + arow * 17 + akp0;
#pragma unroll
            for (int j = 0; j < 8; j++) {
                int col = kk + (akp0 + j) * 2;
                float2 v = make_float2(0.f, 0.f);
                if (gn < N_NODES && col < IN_CH) v = *(const float2*)(xr + 2 * j);
                dstA[j] = __float22half2_rn(v);
            }
        }
        {
            const float* wr = W1 + (size_t)bh * IN_CH + kk + bkp0 * 2;
#pragma unroll
            for (int j = 0; j < 4; j++) {
                int col = kk + (bkp0 + j) * 2;
                float2 v = make_float2(0.f, 0.f);
                if (col < IN_CH) v = *(const float2*)(wr + 2 * j);
                Bs2[bh * 17 + bkp0 + j] = __float22half2_rn(v);
            }
        }
        __syncthreads();
        const int r0 = wid * 16 + g;
#pragma unroll
        for (int ks = 0; ks < 2; ks++) {
            uint32_t A0 = *(const uint32_t*)&As2[r0 * 17 + ks * 8 + tg];
            uint32_t A1 = *(const uint32_t*)&As2[(r0 + 8) * 17 + ks * 8 + tg];
            uint32_t A2 = *(const uint32_t*)&As2[r0 * 17 + ks * 8 + tg + 4];
            uint32_t A3 = *(const uint32_t*)&As2[(r0 + 8) * 17 + ks * 8 + tg + 4];
#pragma unroll
            for (int nt = 0; nt < 8; nt++) {
                uint32_t B0 = *(const uint32_t*)&Bs2[(nt * 8 + g) * 17 + ks * 8 + tg];
                uint32_t B1 = *(const uint32_t*)&Bs2[(nt * 8 + g) * 17 + ks * 8 + tg + 4];
                mma16816(c[nt][0], c[nt][1], c[nt][2], c[nt][3], A0, A1, A2, A3, B0, B1);
            }
        }
        __syncthreads();
    }
    {
        const int row0 = wid * 16 + g;
#pragma unroll
        for (int nt = 0; nt < 8; nt++) {
            int col0 = nt * 8 + tg * 2;
            hs[row0 * 65 + col0]       = fmaxf(c[nt][0] * Ac[col0] + Bc[col0], 0.f);
            hs[row0 * 65 + col0 + 1]   = fmaxf(c[nt][1] * Ac[col0 + 1] + Bc[col0 + 1], 0.f);
            hs[(row0 + 8) * 65 + col0]     = fmaxf(c[nt][2] * Ac[col0] + Bc[col0], 0.f);
            hs[(row0 + 8) * 65 + col0 + 1] = fmaxf(c[nt][3] * Ac[col0 + 1] + Bc[col0 + 1], 0.f);
        }
    }
    for (int idx = t; idx < OUT_CH * HID; idx += 256)
        W2s[(idx >> 6) * 65 + (idx & 63)] = W2[idx];
    __syncthreads();

    const int n = t >> 1, ob = (t & 1) * 20;
    float outv[20];
#pragma unroll
    for (int j = 0; j < 20; j++) outv[j] = b2s[ob + j];
#pragma unroll 8
    for (int cc = 0; cc < HID; cc++) {
        float hv = hs[n * 65 + cc];
#pragma unroll
        for (int j = 0; j < 20; j++) outv[j] += hv * W2s[(ob + j) * 65 + cc];
    }
    int gn = node0 + n;
    if (gn < N_NODES) {
        const float di = g_dinv[gn];
        __half2* dst = (__half2*)g_curh;   // 128B row = RS*4 = 32 half2 per node
#pragma unroll
        for (int j = 0; j < 10; j++)
            dst[(size_t)gn * (RS * 4) + ob / 2 + j] =
                __floats2half2_rn(di * outv[2 * j], di * outv[2 * j + 1]);
    }
}

// ---------------- CSR build ----------------
__global__ void zero_kernel() {
    int i = blockIdx.x * blockDim.x + threadIdx.x;
    if (i < N_NODES) { g_deg[i] = 1; g_fill[i] = 0; }  // 1 = self loop
}

__global__ void hist_kernel(const int* __restrict__ dst) {
    int e = blockIdx.x * blockDim.x + threadIdx.x;
    if (e < N_EDGES) atomicAdd(&g_deg[clamp_node(dst[e])], 1);
}

__device__ __forceinline__ int block_incl_scan(int v, int* warpSums) {
    int lane = threadIdx.x & 31, wid = threadIdx.x >> 5;
#pragma unroll
    for (int o = 1; o < 32; o <<= 1) {
        int nv = __shfl_up_sync(0xFFFFFFFFu, v, o);
        if (lane >= o) v += nv;
    }
    if (lane == 31) warpSums[wid] = v;
    __syncthreads();
    if (wid == 0) {
        int s = (lane < (int)(blockDim.x >> 5)) ? warpSums[lane] : 0;
#pragma unroll
        for (int o = 1; o < 32; o <<= 1) {
            int nv = __shfl_up_sync(0xFFFFFFFFu, s, o);
            if (lane >= o) s += nv;
        }
        warpSums[lane] = s;
    }
    __syncthreads();
    if (wid > 0) v += warpSums[wid - 1];
    return v;
}

__global__ void scan1_kernel() {
    __shared__ int ws[32];
    int i = blockIdx.x * 1024 + threadIdx.x;
    int v = (i < N_NODES) ? (g_deg[i] - 1) : 0;
    int incl = block_incl_scan(v, ws);
    if (i < N_NODES) g_rowptr[i] = incl - v;
    if (threadIdx.x == 1023) g_bsum[blockIdx.x] = incl;
}

__global__ void scan2_kernel(int nb) {
    __shared__ int s[128];
    int i = threadIdx.x;
    int v = (i < nb) ? g_bsum[i] : 0;
    s[i] = v;
    __syncthreads();
    for (int o = 1; o < 128; o <<= 1) {
        int t2 = (i >= o) ? s[i - o] : 0;
        __syncthreads();
        s[i] += t2;
        __syncthreads();
    }
    g_bsum[i] = s[i] - v;
}

__global__ void scan3_kernel() {
    int i = blockIdx.x * blockDim.x + threadIdx.x;
    if (i < N_NODES) {
        g_rowptr[i] += g_bsum[i >> 10];
        g_dinv[i] = rsqrtf((float)g_deg[i]);
    }
    if (i == 0) g_rowptr[N_NODES] = N_EDGES;
}

__global__ void fill_kernel(const int* __restrict__ src, const int* __restrict__ dst) {
    int e = blockIdx.x * blockDim.x + threadIdx.x;
    if (e < N_EDGES) {
        int s = clamp_node(src[e]);
        int d = clamp_node(dst[e]);
        int p = g_rowptr[d] + atomicAdd(&g_fill[d], 1);
        if (p >= 0 && p < N_EDGES) g_col[p] = s;
    }
}

// ---------------- propagation: warp per node; 64-thread blocks; 128B-aligned rows ----------------
template <bool FIRST, bool LAST>
__global__ void prop_kernel(float* __restrict__ out, const float* __restrict__ temp, int k) {
    const uint4* __restrict__ cur = (k & 1) ? g_nexth : g_curh;
    uint4* __restrict__ next = (k & 1) ? g_curh : g_nexth;
    const int warp = (blockIdx.x * blockDim.x + threadIdx.x) >> 5;
    const int lane = threadIdx.x & 31;
    if (warp >= N_NODES) return;
    const int i = warp;
    const int g = lane / 5;          // 0..5 edge group (lane 30,31 idle)
    const int sub = lane - g * 5;    // 0..4 chunk
    const bool grp = (lane < 30);
    const int start = g_rowptr[i], end = g_rowptr[i + 1];
    const float di = g_dinv[i];

    float c[8], acc[8];
#pragma unroll
    for (int j = 0; j < 8; j++) { c[j] = 0.f; acc[j] = 0.f; }
    if (lane < 5) {
        uint4 u = cur[(size_t)i * RS + lane];
        unpack8(u, c);
#pragma unroll
        for (int j = 0; j < 8; j++) acc[j] = c[j];   // self term s_i
    }

    const int gl = (g < 6) ? g : 0;
    const int subc = (sub < 5) ? sub : 0;
    int e0 = start;

    for (; e0 + 30 <= end; e0 += 30) {
        int col = 0;
        if (lane < 30) col = g_col[e0 + lane];
        int srcs[5];
#pragma unroll
        for (int it = 0; it < 5; it++)
            srcs[it] = __shfl_sync(0xFFFFFFFFu, col, it * 6 + gl);
        uint4 us[5];
#pragma unroll
        for (int it = 0; it < 5; it++)
            us[it] = cur[(size_t)srcs[it] * RS + subc];
#pragma unroll
        for (int it = 0; it < 5; it++) {
            float v[8];
            unpack8(us[it], v);
            if (grp) {
#pragma unroll
                for (int j = 0; j < 8; j++) acc[j] += v[j];
            }
        }
    }
    for (; e0 < end; e0 += 6) {
        int col = 0;
        if (lane < 6) {
            int li = e0 + lane;
            col = g_col[li < end ? li : end - 1];
        }
        int src = __shfl_sync(0xFFFFFFFFu, col, gl);
        float wv = (grp && (e0 + g < end)) ? 1.f : 0.f;
        uint4 u = cur[(size_t)src * RS + subc];
        float v[8];
        unpack8(u, v);
#pragma unroll
        for (int j = 0; j < 8; j++) acc[j] += wv * v[j];
    }

    // reduce 6 groups (stride-5 lanes) -> lanes 0..4
#pragma unroll
    for (int j = 0; j < 8; j++) {
        float v = acc[j];
        v += __shfl_down_sync(0xFFFFFFFFu, v, 15);
        float t1 = __shfl_down_sync(0xFFFFFFFFu, v, 5);
        float t2 = __shfl_down_sync(0xFFFFFFFFu, v, 10);
        acc[j] = v + t1 + t2;
    }

    const float tk = temp[k + 1];
    float h[8];
#pragma unroll
    for (int j = 0; j < 8; j++) h[j] = 0.f;
    if (lane < 5) {
#pragma unroll
        for (int j = 0; j < 8; j++) acc[j] *= di;         // nv = di * (sum + s_i)
        if (FIRST) {
            const float t0z = temp[0] / di;                // z = s / di
#pragma unroll
            for (int j = 0; j < 8; j++) h[j] = t0z * c[j] + tk * acc[j];
        } else {
            float4 a = g_hidden4[i * 10 + lane * 2];
            float4 b = g_hidden4[i * 10 + lane * 2 + 1];
            h[0] = a.x + tk * acc[0]; h[1] = a.y + tk * acc[1];
            h[2] = a.z + tk * acc[2]; h[3] = a.w + tk * acc[3];
            h[4] = b.x + tk * acc[4]; h[5] = b.y + tk * acc[5];
            h[6] = b.z + tk * acc[6]; h[7] = b.w + tk * acc[7];
        }
        if (!LAST) {
            float sc[8];
#pragma unroll
            for (int j = 0; j < 8; j++) sc[j] = di * acc[j];   // s' = di * nv
            next[(size_t)i * RS + lane] = pack8(sc);
            g_hidden4[i * 10 + lane * 2]     = make_float4(h[0], h[1], h[2], h[3]);
            g_hidden4[i * 10 + lane * 2 + 1] = make_float4(h[4], h[5], h[6], h[7]);
        }
    }
    if (LAST) {
        float m = -1e30f;
        if (lane < 5) {
#pragma unroll
            for (int j = 0; j < 8; j++) m = fmaxf(m, h[j]);
        }
#pragma unroll
        for (int o = 1; o < 8; o <<= 1) m = fmaxf(m, __shfl_xor_sync(0xFFFFFFFFu, m, o));
        float s = 0.f;
        if (lane < 5) {
#pragma unroll
            for (int j = 0; j < 8; j++) s += expf(h[j] - m);
        }
#pragma unroll
        for (int o = 1; o < 8; o <<= 1) s += __shfl_xor_sync(0xFFFFFFFFu, s, o);
        const float lse = m + logf(s);
        if (lane < 5) {
            float4* o4 = (float4*)(out + (size_t)i * OUT_CH + lane * 8);
            o4[0] = make_float4(h[0] - lse, h[1] - lse, h[2] - lse, h[3] - lse);
            o4[1] = make_float4(h[4] - lse, h[5] - lse, h[6] - lse, h[7] - lse);
        }
    }
}

// ---------------- launch: kernel launches ONLY ----------------
extern "C" void kernel_launch(void* const* d_in, const int* in_sizes, int n_in,
                              void* d_out, int out_size) {
    const float* x    = (const float*)d_in[0];
    const int*   ei   = (const int*)d_in[1];  // [2, N_EDGES] int32
    const float* W1   = (const float*)d_in[2];
    const float* b1   = (const float*)d_in[3];
    const float* W2   = (const float*)d_in[4];
    const float* b2   = (const float*)d_in[5];
    const float* gam  = (const float*)d_in[6];
    const float* bet  = (const float*)d_in[7];
    const float* mea  = (const float*)d_in[8];
    const float* var  = (const float*)d_in[9];
    const float* temp = (const float*)d_in[10];
    float* out = (float*)d_out;
    const int* srcp = ei;
    const int* dstp = ei + N_EDGES;

    // CSR first (stem needs g_dinv)
    zero_kernel<<<(N_NODES + 255) / 256, 256>>>();
    hist_kernel<<<(N_EDGES + 255) / 256, 256>>>(dstp);
    const int nb = (N_NODES + 1023) / 1024;  // 98
    scan1_kernel<<<nb, 1024>>>();
    scan2_kernel<<<1, 128>>>(nb);
    scan3_kernel<<<(N_NODES + 255) / 256, 256>>>();
    fill_kernel<<<(N_EDGES + 255) / 256, 256>>>(srcp, dstp);

    stem_kernel<<<(N_NODES + 127) / 128, 256>>>(x, W1, b1, W2, b2, gam, bet, mea, var);

    const int pgrid = (N_NODES * 32 + 63) / 64;
    prop_kernel<true, false><<<pgrid, 64>>>(nullptr, temp, 0);
    for (int k = 1; k < K_HOPS - 1; k++)
        prop_kernel<false, false><<<pgrid, 64>>>(nullptr, temp, k);
    prop_kernel<false, true><<<pgrid, 64>>>(out, temp, K_HOPS - 1);
}

// round 16
// speedup vs baseline: 1.6594x; 1.0130x over previous
#include <cuda_runtime.h>
#include <cuda_fp16.h>
#include <cstdint>

#define N_NODES 100000
#define N_EDGES 3200000
#define IN_CH   500
#define HID     64
#define OUT_CH  40
#define K_HOPS  10
#define RS      8    // uint4 per feature row: 128B padded (5 chunks used)
#define NB_SCAN 98   // scan blocks (1024 threads each)

// ---------------- scratch ----------------
__device__ int    g_deg[N_NODES];
__device__ int    g_fill[N_NODES];
__device__ int    g_rowptr[N_NODES + 1];
__device__ float  g_dinv[N_NODES];
__device__ int    g_col[N_EDGES];             // CSR col (src); weight folded into features
__device__ uint4  g_curh[N_NODES * RS];       // scaled fp16 features, 128B/row (ping)
__device__ uint4  g_nexth[N_NODES * RS];      // (pong)
__device__ float4 g_hidden4[N_NODES * 10];    // fp32 hidden accumulator
__device__ int    g_bsum[128];                // raw per-block sums from scan1

__device__ __forceinline__ int clamp_node(int v) {
    return v < 0 ? 0 : (v >= N_NODES ? N_NODES - 1 : v);
}

__device__ __forceinline__ void unpack8(uint4 u, float* f) {
    float2 a = __half22float2(*(__half2*)&u.x);
    float2 b = __half22float2(*(__half2*)&u.y);
    float2 c = __half22float2(*(__half2*)&u.z);
    float2 d = __half22float2(*(__half2*)&u.w);
    f[0] = a.x; f[1] = a.y; f[2] = b.x; f[3] = b.y;
    f[4] = c.x; f[5] = c.y; f[6] = d.x; f[7] = d.y;
}

__device__ __forceinline__ uint4 pack8(const float* f) {
    uint4 u;
    *(__half2*)&u.x = __floats2half2_rn(f[0], f[1]);
    *(__half2*)&u.y = __floats2half2_rn(f[2], f[3]);
    *(__half2*)&u.z = __floats2half2_rn(f[4], f[5]);
    *(__half2*)&u.w = __floats2half2_rn(f[6], f[7]);
    return u;
}

__device__ __forceinline__ void mma16816(float& c0, float& c1, float& c2, float& c3,
                                         uint32_t a0, uint32_t a1, uint32_t a2, uint32_t a3,
                                         uint32_t b0, uint32_t b1) {
    asm volatile(
        "mma.sync.aligned.m16n8k16.row.col.f32.f16.f16.f32 "
        "{%0,%1,%2,%3}, {%4,%5,%6,%7}, {%8,%9}, {%0,%1,%2,%3};"
        : "+f"(c0), "+f"(c1), "+f"(c2), "+f"(c3)
        : "r"(a0), "r"(a1), "r"(a2), "r"(a3), "r"(b0), "r"(b1));
}

// ---------------- stem: BM=128, BK=32; HMMA m16n8k16; float4 global loads ----------------
__global__ void stem_kernel(const float* __restrict__ x, const float* __restrict__ W1,
                            const float* __restrict__ b1, const float* __restrict__ W2,
                            const float* __restrict__ b2, const float* __restrict__ gamma,
                            const float* __restrict__ beta, const float* __restrict__ mean,
                            const float* __restrict__ var) {
    __shared__ float buf[10920];
    __shared__ float Ac[HID], Bc[HID], b2s[OUT_CH];
    __half2* As2 = (__half2*)buf;               // [128][17] = 2176 slots
    __half2* Bs2 = (__half2*)buf + 2176;        // [64][17]  = 1088 slots
    float* hs  = buf;                           // [128][65] (phase 2)
    float* W2s = buf + 8320;                    // [40][65]

    const int t = threadIdx.x;        // 256 threads = 8 warps
    const int node0 = blockIdx.x * 128;
    const int wid = t >> 5, lane = t & 31;
    const int g = lane >> 2, tg = lane & 3;

    if (t < HID) {
        float A = gamma[t] * rsqrtf(var[t] + 1e-5f);
        Ac[t] = A;
        Bc[t] = (b1[t] - mean[t]) * A + beta[t];
    }
    if (t < OUT_CH) b2s[t] = b2[t];

    float c[8][4];
#pragma unroll
    for (int nt = 0; nt < 8; nt++)
#pragma unroll
        for (int q = 0; q < 4; q++) c[nt][q] = 0.f;

    const int arow = t >> 1;
    const int akp0 = (t & 1) * 8;     // half2-k offset 0 or 8 (16 floats)
    const int bh = t & 63;
    const int bkp0 = (t >> 6) * 4;    // half2-k offset (8 floats)

    for (int kk = 0; kk < IN_CH; kk += 32) {
        // As2 loader: 4x float4 (16B-aligned: row base 2000B, offset 64B multiples)
        {
            int gn = node0 + arow;
            const float* xr = x + (size_t)gn * IN_CH + kk + akp0 * 2;
            __half2* dstA = As2 + arow * 17 + akp0;
#pragma unroll
            for (int j = 0; j < 4; j++) {
                int col = kk + akp0 * 2 + 4 * j;
                float4 v = make_float4(0.f, 0.f, 0.f, 0.f);
                if (gn < N_NODES && col + 3 < IN_CH) v = *(const float4*)(xr + 4 * j);
                else if (gn < N_NODES) {
                    // ragged tail (IN_CH=500): per-element guard
                    float tmp[4] = {0.f, 0.f, 0.f, 0.f};
#pragma unroll
                    for (int q = 0; q < 4; q++)
                        if (col + q < IN_CH) tmp[q] = xr[4 * j + q];
                    v = make_float4(tmp[0], tmp[1], tmp[2], tmp[3]);
                }
                dstA[2 * j]     = __floats2half2_rn(v.x, v.y);
                dstA[2 * j + 1] = __floats2half2_rn(v.z, v.w);
            }
        }
        // Bs2 loader: 2x float4 (row base 2000B, offset 32B multiples)
        {
            const float* wr = W1 + (size_t)bh * IN_CH + kk + bkp0 * 2;
#pragma unroll
            for (int j = 0; j < 2; j++) {
                int col = kk + bkp0 * 2 + 4 * j;
                float4 v = make_float4(0.f, 0.f, 0.f, 0.f);
                if (col + 3 < IN_CH) v = *(const float4*)(wr + 4 * j);
                else {
                    float tmp[4] = {0.f, 0.f, 0.f, 0.f};
#pragma unroll
                    for (int q = 0; q < 4; q++)
                        if (col + q < IN_CH) tmp[q] = wr[4 * j + q];
                    v = make_float4(tmp[0], tmp[1], tmp[2], tmp[3]);
                }
                Bs2[bh * 17 + bkp0 + 2 * j]     = __floats2half2_rn(v.x, v.y);
                Bs2[bh * 17 + bkp0 + 2 * j + 1] = __floats2half2_rn(v.z, v.w);
            }
        }
        __syncthreads();
        const int r0 = wid * 16 + g;
#pragma unroll
        for (int ks = 0; ks < 2; ks++) {
            uint32_t A0 = *(const uint32_t*)&As2[r0 * 17 + ks * 8 + tg];
            uint32_t A1 = *(const uint32_t*)&As2[(r0 + 8) * 17 + ks * 8 + tg];
            uint32_t A2 = *(const uint32_t*)&As2[r0 * 17 + ks * 8 + tg + 4];
            uint32_t A3 = *(const uint32_t*)&As2[(r0 + 8) * 17 + ks * 8 + tg + 4];
#pragma unroll
            for (int nt = 0; nt < 8; nt++) {
                uint32_t B0 = *(const uint32_t*)&Bs2[(nt * 8 + g) * 17 + ks * 8 + tg];
                uint32_t B1 = *(const uint32_t*)&Bs2[(nt * 8 + g) * 17 + ks * 8 + tg + 4];
                mma16816(c[nt][0], c[nt][1], c[nt][2], c[nt][3], A0, A1, A2, A3, B0, B1);
            }
        }
        __syncthreads();
    }
    {
        const int row0 = wid * 16 + g;
#pragma unroll
        for (int nt = 0; nt < 8; nt++) {
            int col0 = nt * 8 + tg * 2;
            hs[row0 * 65 + col0]       = fmaxf(c[nt][0] * Ac[col0] + Bc[col0], 0.f);
            hs[row0 * 65 + col0 + 1]   = fmaxf(c[nt][1] * Ac[col0 + 1] + Bc[col0 + 1], 0.f);
            hs[(row0 + 8) * 65 + col0]     = fmaxf(c[nt][2] * Ac[col0] + Bc[col0], 0.f);
            hs[(row0 + 8) * 65 + col0 + 1] = fmaxf(c[nt][3] * Ac[col0 + 1] + Bc[col0 + 1], 0.f);
        }
    }
    for (int idx = t; idx < OUT_CH * HID; idx += 256)
        W2s[(idx >> 6) * 65 + (idx & 63)] = W2[idx];
    __syncthreads();

    const int n = t >> 1, ob = (t & 1) * 20;
    float outv[20];
#pragma unroll
    for (int j = 0; j < 20; j++) outv[j] = b2s[ob + j];
#pragma unroll 8
    for (int cc = 0; cc < HID; cc++) {
        float hv = hs[n * 65 + cc];
#pragma unroll
        for (int j = 0; j < 20; j++) outv[j] += hv * W2s[(ob + j) * 65 + cc];
    }
    int gn = node0 + n;
    if (gn < N_NODES) {
        const float di = g_dinv[gn];
        __half2* dst = (__half2*)g_curh;   // 128B row = RS*4 = 32 half2 per node
#pragma unroll
        for (int j = 0; j < 10; j++)
            dst[(size_t)gn * (RS * 4) + ob / 2 + j] =
                __floats2half2_rn(di * outv[2 * j], di * outv[2 * j + 1]);
    }
}

// ---------------- CSR build ----------------
__global__ void zero_kernel() {
    int i = blockIdx.x * blockDim.x + threadIdx.x;
    if (i < N_NODES) { g_deg[i] = 1; g_fill[i] = 0; }  // 1 = self loop
}

__global__ void hist_kernel(const int* __restrict__ dst) {
    int e = blockIdx.x * blockDim.x + threadIdx.x;
    if (e < N_EDGES) atomicAdd(&g_deg[clamp_node(dst[e])], 1);
}

__device__ __forceinline__ int block_incl_scan(int v, int* warpSums) {
    int lane = threadIdx.x & 31, wid = threadIdx.x >> 5;
#pragma unroll
    for (int o = 1; o < 32; o <<= 1) {
        int nv = __shfl_up_sync(0xFFFFFFFFu, v, o);
        if (lane >= o) v += nv;
    }
    if (lane == 31) warpSums[wid] = v;
    __syncthreads();
    if (wid == 0) {
        int s = (lane < (int)(blockDim.x >> 5)) ? warpSums[lane] : 0;
#pragma unroll
        for (int o = 1; o < 32; o <<= 1) {
            int nv = __shfl_up_sync(0xFFFFFFFFu, s, o);
            if (lane >= o) s += nv;
        }
        warpSums[lane] = s;
    }
    __syncthreads();
    if (wid > 0) v += warpSums[wid - 1];
    return v;
}

__global__ void scan1_kernel() {
    __shared__ int ws[32];
    int i = blockIdx.x * 1024 + threadIdx.x;
    int v = (i < N_NODES) ? (g_deg[i] - 1) : 0;
    int incl = block_incl_scan(v, ws);
    if (i < N_NODES) g_rowptr[i] = incl - v;   // local exclusive prefix
    if (threadIdx.x == 1023) g_bsum[blockIdx.x] = incl;   // raw block sum
}

// scan3 folds the 98-element block-sum prefix in per-block (replaces scan2)
__global__ void scan3_kernel() {
    __shared__ int ps[NB_SCAN];
    // warp 0 computes exclusive prefix of g_bsum[0..97] in smem
    if (threadIdx.x < 32) {
        int lane = threadIdx.x;
        int run = 0;
        // sequential-ish scan over 98 entries by a single warp (4 chunks of 32)
        for (int base = 0; base < NB_SCAN; base += 32) {
            int idx = base + lane;
            int v = (idx < NB_SCAN) ? g_bsum[idx] : 0;
            int incl = v;
#pragma unroll
            for (int o = 1; o < 32; o <<= 1) {
                int nv = __shfl_up_sync(0xFFFFFFFFu, incl, o);
                if (lane >= o) incl += nv;
            }
            if (idx < NB_SCAN) ps[idx] = run + incl - v;   // exclusive
            run += __shfl_sync(0xFFFFFFFFu, incl, 31);
        }
    }
    __syncthreads();
    int i = blockIdx.x * blockDim.x + threadIdx.x;
    if (i < N_NODES) {
        g_rowptr[i] += ps[i >> 10];
        g_dinv[i] = rsqrtf((float)g_deg[i]);
    }
    if (i == 0) g_rowptr[N_NODES] = N_EDGES;
}

__global__ void fill_kernel(const int* __restrict__ src, const int* __restrict__ dst) {
    int e = blockIdx.x * blockDim.x + threadIdx.x;
    if (e < N_EDGES) {
        int s = clamp_node(src[e]);
        int d = clamp_node(dst[e]);
        int p = g_rowptr[d] + atomicAdd(&g_fill[d], 1);
        if (p >= 0 && p < N_EDGES) g_col[p] = s;
    }
}

// ---------------- propagation: warp per node; 64-thread blocks; 30-edge batches ----------------
template <bool FIRST, bool LAST>
__global__ void prop_kernel(float* __restrict__ out, const float* __restrict__ temp, int k) {
    const uint4* __restrict__ cur = (k & 1) ? g_nexth : g_curh;
    uint4* __restrict__ next = (k & 1) ? g_curh : g_nexth;
    const int warp = (blockIdx.x * blockDim.x + threadIdx.x) >> 5;
    const int lane = threadIdx.x & 31;
    if (warp >= N_NODES) return;
    const int i = warp;
    const int g = lane / 5;          // 0..5 edge group (lane 30,31 idle)
    const int sub = lane - g * 5;    // 0..4 chunk
    const bool grp = (lane < 30);
    const int start = g_rowptr[i], end = g_rowptr[i + 1];
    const float di = g_dinv[i];

    float c[8], acc[8];
#pragma unroll
    for (int j = 0; j < 8; j++) { c[j] = 0.f; acc[j] = 0.f; }
    if (lane < 5) {
        uint4 u = cur[(size_t)i * RS + lane];
        unpack8(u, c);
#pragma unroll
        for (int j = 0; j < 8; j++) acc[j] = c[j];   // self term s_i
    }

    const int gl = (g < 6) ? g : 0;
    const int subc = (sub < 5) ? sub : 0;
    int e0 = start;

    for (; e0 + 30 <= end; e0 += 30) {
        int col = 0;
        if (lane < 30) col = g_col[e0 + lane];
        int srcs[5];
#pragma unroll
        for (int it = 0; it < 5; it++)
            srcs[it] = __shfl_sync(0xFFFFFFFFu, col, it * 6 + gl);
        uint4 us[5];
#pragma unroll
        for (int it = 0; it < 5; it++)
            us[it] = cur[(size_t)srcs[it] * RS + subc];
#pragma unroll
        for (int it = 0; it < 5; it++) {
            float v[8];
            unpack8(us[it], v);
            if (grp) {
#pragma unroll
                for (int j = 0; j < 8; j++) acc[j] += v[j];
            }
        }
    }
    for (; e0 < end; e0 += 6) {
        int col = 0;
        if (lane < 6) {
            int li = e0 + lane;
            col = g_col[li < end ? li : end - 1];
        }
        int src = __shfl_sync(0xFFFFFFFFu, col, gl);
        float wv = (grp && (e0 + g < end)) ? 1.f : 0.f;
        uint4 u = cur[(size_t)src * RS + subc];
        float v[8];
        unpack8(u, v);
#pragma unroll
        for (int j = 0; j < 8; j++) acc[j] += wv * v[j];
    }

    // reduce 6 groups (stride-5 lanes) -> lanes 0..4
#pragma unroll
    for (int j = 0; j < 8; j++) {
        float v = acc[j];
        v += __shfl_down_sync(0xFFFFFFFFu, v, 15);
        float t1 = __shfl_down_sync(0xFFFFFFFFu, v, 5);
        float t2 = __shfl_down_sync(0xFFFFFFFFu, v, 10);
        acc[j] = v + t1 + t2;
    }

    const float tk = temp[k + 1];
    float h[8];
#pragma unroll
    for (int j = 0; j < 8; j++) h[j] = 0.f;
    if (lane < 5) {
#pragma unroll
        for (int j = 0; j < 8; j++) acc[j] *= di;         // nv = di * (sum + s_i)
        if (FIRST) {
            const float t0z = temp[0] / di;                // z = s / di
#pragma unroll
            for (int j = 0; j < 8; j++) h[j] = t0z * c[j] + tk * acc[j];
        } else {
            float4 a = g_hidden4[i * 10 + lane * 2];
            float4 b = g_hidden4[i * 10 + lane * 2 + 1];
            h[0] = a.x + tk * acc[0]; h[1] = a.y + tk * acc[1];
            h[2] = a.z + tk * acc[2]; h[3] = a.w + tk * acc[3];
            h[4] = b.x + tk * acc[4]; h[5] = b.y + tk * acc[5];
            h[6] = b.z + tk * acc[6]; h[7] = b.w + tk * acc[7];
        }
        if (!LAST) {
            float sc[8];
#pragma unroll
            for (int j = 0; j < 8; j++) sc[j] = di * acc[j];   // s' = di * nv
            next[(size_t)i * RS + lane] = pack8(sc);
            g_hidden4[i * 10 + lane * 2]     = make_float4(h[0], h[1], h[2], h[3]);
            g_hidden4[i * 10 + lane * 2 + 1] = make_float4(h[4], h[5], h[6], h[7]);
        }
    }
    if (LAST) {
        float m = -1e30f;
        if (lane < 5) {
#pragma unroll
            for (int j = 0; j < 8; j++) m = fmaxf(m, h[j]);
        }
#pragma unroll
        for (int o = 1; o < 8; o <<= 1) m = fmaxf(m, __shfl_xor_sync(0xFFFFFFFFu, m, o));
        float s = 0.f;
        if (lane < 5) {
#pragma unroll
            for (int j = 0; j < 8; j++) s += expf(h[j] - m);
        }
#pragma unroll
        for (int o = 1; o < 8; o <<= 1) s += __shfl_xor_sync(0xFFFFFFFFu, s, o);
        const float lse = m + logf(s);
        if (lane < 5) {
            float4* o4 = (float4*)(out + (size_t)i * OUT_CH + lane * 8);
            o4[0] = make_float4(h[0] - lse, h[1] - lse, h[2] - lse, h[3] - lse);
            o4[1] = make_float4(h[4] - lse, h[5] - lse, h[6] - lse, h[7] - lse);
        }
    }
}

// ---------------- launch: kernel launches ONLY ----------------
extern "C" void kernel_launch(void* const* d_in, const int* in_sizes, int n_in,
                              void* d_out, int out_size) {
    const float* x    = (const float*)d_in[0];
    const int*   ei   = (const int*)d_in[1];  // [2, N_EDGES] int32
    const float* W1   = (const float*)d_in[2];
    const float* b1   = (const float*)d_in[3];
    const float* W2   = (const float*)d_in[4];
    const float* b2   = (const float*)d_in[5];
    const float* gam  = (const float*)d_in[6];
    const float* bet  = (const float*)d_in[7];
    const float* mea  = (const float*)d_in[8];
    const float* var  = (const float*)d_in[9];
    const float* temp = (const float*)d_in[10];
    float* out = (float*)d_out;
    const int* srcp = ei;
    const int* dstp = ei + N_EDGES;

    // CSR first (stem needs g_dinv)
    zero_kernel<<<(N_NODES + 255) / 256, 256>>>();
    hist_kernel<<<(N_EDGES + 255) / 256, 256>>>(dstp);
    scan1_kernel<<<NB_SCAN, 1024>>>();
    scan3_kernel<<<(N_NODES + 1023) / 1024, 1024>>>();
    fill_kernel<<<(N_EDGES + 255) / 256, 256>>>(srcp, dstp);

    stem_kernel<<<(N_NODES + 127) / 128, 256>>>(x, W1, b1, W2, b2, gam, bet, mea, var);

    const int pgrid = (N_NODES * 32 + 63) / 64;
    prop_kernel<true, false><<<pgrid, 64>>>(nullptr, temp, 0);
    for (int k = 1; k < K_HOPS - 1; k++)
        prop_kernel<false, false><<<pgrid, 64>>>(nullptr, temp, k);
    prop_kernel<false, true><<<pgrid, 64>>>(out, temp, K_HOPS - 1);
}

// round 17
// speedup vs baseline: 1.6825x; 1.0140x over previous
#include <cuda_runtime.h>
#include <cuda_fp16.h>
#include <cstdint>

#define N_NODES 100000
#define N_EDGES 3200000
#define IN_CH   500
#define HID     64
#define OUT_CH  40
#define K_HOPS  10
#define RS      8    // uint4 per feature row: 128B padded (5 chunks used)
#define NB_SCAN 98   // scan blocks (1024 threads each)

// ---------------- scratch ----------------
__device__ int    g_deg[N_NODES];
__device__ int    g_fill[N_NODES];            // fill cursor, pre-seeded with rowptr
__device__ int    g_rowptr[N_NODES + 1];
__device__ float  g_dinv[N_NODES];
__device__ int    g_col[N_EDGES];             // CSR col (src); weight folded into features
__device__ uint4  g_curh[N_NODES * RS];       // scaled fp16 features, 128B/row (ping)
__device__ uint4  g_nexth[N_NODES * RS];      // (pong)
__device__ uint4  g_hiddenh[N_NODES * 5];     // fp16 hidden accumulator, 80B packed rows
__device__ int    g_bsum[128];                // raw per-block sums from scan1

__device__ __forceinline__ int clamp_node(int v) {
    return v < 0 ? 0 : (v >= N_NODES ? N_NODES - 1 : v);
}

__device__ __forceinline__ void unpack8(uint4 u, float* f) {
    float2 a = __half22float2(*(__half2*)&u.x);
    float2 b = __half22float2(*(__half2*)&u.y);
    float2 c = __half22float2(*(__half2*)&u.z);
    float2 d = __half22float2(*(__half2*)&u.w);
    f[0] = a.x; f[1] = a.y; f[2] = b.x; f[3] = b.y;
    f[4] = c.x; f[5] = c.y; f[6] = d.x; f[7] = d.y;
}

__device__ __forceinline__ uint4 pack8(const float* f) {
    uint4 u;
    *(__half2*)&u.x = __floats2half2_rn(f[0], f[1]);
    *(__half2*)&u.y = __floats2half2_rn(f[2], f[3]);
    *(__half2*)&u.z = __floats2half2_rn(f[4], f[5]);
    *(__half2*)&u.w = __floats2half2_rn(f[6], f[7]);
    return u;
}

__device__ __forceinline__ void mma16816(float& c0, float& c1, float& c2, float& c3,
                                         uint32_t a0, uint32_t a1, uint32_t a2, uint32_t a3,
                                         uint32_t b0, uint32_t b1) {
    asm volatile(
        "mma.sync.aligned.m16n8k16.row.col.f32.f16.f16.f32 "
        "{%0,%1,%2,%3}, {%4,%5,%6,%7}, {%8,%9}, {%0,%1,%2,%3};"
        : "+f"(c0), "+f"(c1), "+f"(c2), "+f"(c3)
        : "r"(a0), "r"(a1), "r"(a2), "r"(a3), "r"(b0), "r"(b1));
}

// ---------------- stem: BM=128, BK=32; HMMA m16n8k16; float4 global loads ----------------
__global__ void stem_kernel(const float* __restrict__ x, const float* __restrict__ W1,
                            const float* __restrict__ b1, const float* __restrict__ W2,
                            const float* __restrict__ b2, const float* __restrict__ gamma,
                            const float* __restrict__ beta, const float* __restrict__ mean,
                            const float* __restrict__ var) {
    __shared__ float buf[10920];
    __shared__ float Ac[HID], Bc[HID], b2s[OUT_CH];
    __half2* As2 = (__half2*)buf;               // [128][17] = 2176 slots
    __half2* Bs2 = (__half2*)buf + 2176;        // [64][17]  = 1088 slots
    float* hs  = buf;                           // [128][65] (phase 2)
    float* W2s = buf + 8320;                    // [40][65]

    const int t = threadIdx.x;        // 256 threads = 8 warps
    const int node0 = blockIdx.x * 128;
    const int wid = t >> 5, lane = t & 31;
    const int g = lane >> 2, tg = lane & 3;

    if (t < HID) {
        float A = gamma[t] * rsqrtf(var[t] + 1e-5f);
        Ac[t] = A;
        Bc[t] = (b1[t] - mean[t]) * A + beta[t];
    }
    if (t < OUT_CH) b2s[t] = b2[t];

    float c[8][4];
#pragma unroll
    for (int nt = 0; nt < 8; nt++)
#pragma unroll
        for (int q = 0; q < 4; q++) c[nt][q] = 0.f;

    const int arow = t >> 1;
    const int akp0 = (t & 1) * 8;
    const int bh = t & 63;
    const int bkp0 = (t >> 6) * 4;

    for (int kk = 0; kk < IN_CH; kk += 32) {
        {
            int gn = node0 + arow;
            const float* xr = x + (size_t)gn * IN_CH + kk + akp0 * 2;
            __half2* dstA = As2 + arow * 17 + akp0;
#pragma unroll
            for (int j = 0; j < 4; j++) {
                int col = kk + akp0 * 2 + 4 * j;
                float4 v = make_float4(0.f, 0.f, 0.f, 0.f);
                if (gn < N_NODES && col + 3 < IN_CH) v = *(const float4*)(xr + 4 * j);
                else if (gn < N_NODES) {
                    float tmp[4] = {0.f, 0.f, 0.f, 0.f};
#pragma unroll
                    for (int q = 0; q < 4; q++)
                        if (col + q < IN_CH) tmp[q] = xr[4 * j + q];
                    v = make_float4(tmp[0], tmp[1], tmp[2], tmp[3]);
                }
                dstA[2 * j]     = __floats2half2_rn(v.x, v.y);
                dstA[2 * j + 1] = __floats2half2_rn(v.z, v.w);
            }
        }
        {
            const float* wr = W1 + (size_t)bh * IN_CH + kk + bkp0 * 2;
#pragma unroll
            for (int j = 0; j < 2; j++) {
                int col = kk + bkp0 * 2 + 4 * j;
                float4 v = make_float4(0.f, 0.f, 0.f, 0.f);
                if (col + 3 < IN_CH) v = *(const float4*)(wr + 4 * j);
                else {
                    float tmp[4] = {0.f, 0.f, 0.f, 0.f};
#pragma unroll
                    for (int q = 0; q < 4; q++)
                        if (col + q < IN_CH) tmp[q] = wr[4 * j + q];
                    v = make_float4(tmp[0], tmp[1], tmp[2], tmp[3]);
                }
                Bs2[bh * 17 + bkp0 + 2 * j]     = __floats2half2_rn(v.x, v.y);
                Bs2[bh * 17 + bkp0 + 2 * j + 1] = __floats2half2_rn(v.z, v.w);
            }
        }
        __syncthreads();
        const int r0 = wid * 16 + g;
#pragma unroll
        for (int ks = 0; ks < 2; ks++) {
            uint32_t A0 = *(const uint32_t*)&As2[r0 * 17 + ks * 8 + tg];
            uint32_t A1 = *(const uint32_t*)&As2[(r0 + 8) * 17 + ks * 8 + tg];
            uint32_t A2 = *(const uint32_t*)&As2[r0 * 17 + ks * 8 + tg + 4];
            uint32_t A3 = *(const uint32_t*)&As2[(r0 + 8) * 17 + ks * 8 + tg + 4];
#pragma unroll
            for (int nt = 0; nt < 8; nt++) {
                uint32_t B0 = *(const uint32_t*)&Bs2[(nt * 8 + g) * 17 + ks * 8 + tg];
                uint32_t B1 = *(const uint32_t*)&Bs2[(nt * 8 + g) * 17 + ks * 8 + tg + 4];
                mma16816(c[nt][0], c[nt][1], c[nt][2], c[nt][3], A0, A1, A2, A3, B0, B1);
            }
        }
        __syncthreads();
    }
    {
        const int row0 = wid * 16 + g;
#pragma unroll
        for (int nt = 0; nt < 8; nt++) {
            int col0 = nt * 8 + tg * 2;
            hs[row0 * 65 + col0]       = fmaxf(c[nt][0] * Ac[col0] + Bc[col0], 0.f);
            hs[row0 * 65 + col0 + 1]   = fmaxf(c[nt][1] * Ac[col0 + 1] + Bc[col0 + 1], 0.f);
            hs[(row0 + 8) * 65 + col0]     = fmaxf(c[nt][2] * Ac[col0] + Bc[col0], 0.f);
            hs[(row0 + 8) * 65 + col0 + 1] = fmaxf(c[nt][3] * Ac[col0 + 1] + Bc[col0 + 1], 0.f);
        }
    }
    for (int idx = t; idx < OUT_CH * HID; idx += 256)
        W2s[(idx >> 6) * 65 + (idx & 63)] = W2[idx];
    __syncthreads();

    const int n = t >> 1, ob = (t & 1) * 20;
    float outv[20];
#pragma unroll
    for (int j = 0; j < 20; j++) outv[j] = b2s[ob + j];
#pragma unroll 8
    for (int cc = 0; cc < HID; cc++) {
        float hv = hs[n * 65 + cc];
#pragma unroll
        for (int j = 0; j < 20; j++) outv[j] += hv * W2s[(ob + j) * 65 + cc];
    }
    int gn = node0 + n;
    if (gn < N_NODES) {
        const float di = g_dinv[gn];
        __half2* dst = (__half2*)g_curh;   // 128B row = RS*4 = 32 half2 per node
#pragma unroll
        for (int j = 0; j < 10; j++)
            dst[(size_t)gn * (RS * 4) + ob / 2 + j] =
                __floats2half2_rn(di * outv[2 * j], di * outv[2 * j + 1]);
    }
}

// ---------------- CSR build ----------------
__global__ void zero_kernel() {
    int i = blockIdx.x * blockDim.x + threadIdx.x;
    if (i < N_NODES) g_deg[i] = 1;   // 1 = self loop
}

__global__ void hist_kernel(const int* __restrict__ dst) {
    int e = blockIdx.x * blockDim.x + threadIdx.x;
    if (e < N_EDGES) atomicAdd(&g_deg[clamp_node(dst[e])], 1);
}

__device__ __forceinline__ int block_incl_scan(int v, int* warpSums) {
    int lane = threadIdx.x & 31, wid = threadIdx.x >> 5;
#pragma unroll
    for (int o = 1; o < 32; o <<= 1) {
        int nv = __shfl_up_sync(0xFFFFFFFFu, v, o);
        if (lane >= o) v += nv;
    }
    if (lane == 31) warpSums[wid] = v;
    __syncthreads();
    if (wid == 0) {
        int s = (lane < (int)(blockDim.x >> 5)) ? warpSums[lane] : 0;
#pragma unroll
        for (int o = 1; o < 32; o <<= 1) {
            int nv = __shfl_up_sync(0xFFFFFFFFu, s, o);
            if (lane >= o) s += nv;
        }
        warpSums[lane] = s;
    }
    __syncthreads();
    if (wid > 0) v += warpSums[wid - 1];
    return v;
}

__global__ void scan1_kernel() {
    __shared__ int ws[32];
    int i = blockIdx.x * 1024 + threadIdx.x;
    int v = (i < N_NODES) ? (g_deg[i] - 1) : 0;
    int incl = block_incl_scan(v, ws);
    if (i < N_NODES) g_rowptr[i] = incl - v;   // local exclusive prefix
    if (threadIdx.x == 1023) g_bsum[blockIdx.x] = incl;   // raw block sum
}

// scan3: fold block-sum prefix, finalize rowptr, seed fill cursors, compute dinv
__global__ void scan3_kernel() {
    __shared__ int ps[NB_SCAN];
    if (threadIdx.x < 32) {
        int lane = threadIdx.x;
        int run = 0;
        for (int base = 0; base < NB_SCAN; base += 32) {
            int idx = base + lane;
            int v = (idx < NB_SCAN) ? g_bsum[idx] : 0;
            int incl = v;
#pragma unroll
            for (int o = 1; o < 32; o <<= 1) {
                int nv = __shfl_up_sync(0xFFFFFFFFu, incl, o);
                if (lane >= o) incl += nv;
            }
            if (idx < NB_SCAN) ps[idx] = run + incl - v;   // exclusive
            run += __shfl_sync(0xFFFFFFFFu, incl, 31);
        }
    }
    __syncthreads();
    int i = blockIdx.x * blockDim.x + threadIdx.x;
    if (i < N_NODES) {
        int rp = g_rowptr[i] + ps[i >> 10];
        g_rowptr[i] = rp;
        g_fill[i] = rp;                         // seed fill cursor with rowptr
        g_dinv[i] = rsqrtf((float)g_deg[i]);
    }
    if (i == 0) g_rowptr[N_NODES] = N_EDGES;
}

__global__ void fill_kernel(const int* __restrict__ src, const int* __restrict__ dst) {
    int e = blockIdx.x * blockDim.x + threadIdx.x;
    if (e < N_EDGES) {
        int s = clamp_node(src[e]);
        int d = clamp_node(dst[e]);
        int p = atomicAdd(&g_fill[d], 1);       // cursor pre-seeded with rowptr[d]
        if (p >= 0 && p < N_EDGES) g_col[p] = s;
    }
}

// ---------------- propagation: warp per node; 64-thread blocks; fp16 hidden ----------------
template <bool FIRST, bool LAST>
__global__ void prop_kernel(float* __restrict__ out, const float* __restrict__ temp, int k) {
    const uint4* __restrict__ cur = (k & 1) ? g_nexth : g_curh;
    uint4* __restrict__ next = (k & 1) ? g_curh : g_nexth;
    const int warp = (blockIdx.x * blockDim.x + threadIdx.x) >> 5;
    const int lane = threadIdx.x & 31;
    if (warp >= N_NODES) return;
    const int i = warp;
    const int g = lane / 5;          // 0..5 edge group (lane 30,31 idle)
    const int sub = lane - g * 5;    // 0..4 chunk
    const bool grp = (lane < 30);
    const int start = g_rowptr[i], end = g_rowptr[i + 1];
    const float di = g_dinv[i];

    float c[8], acc[8];
#pragma unroll
    for (int j = 0; j < 8; j++) { c[j] = 0.f; acc[j] = 0.f; }
    if (lane < 5) {
        uint4 u = cur[(size_t)i * RS + lane];
        unpack8(u, c);
#pragma unroll
        for (int j = 0; j < 8; j++) acc[j] = c[j];   // self term s_i
    }

    const int gl = (g < 6) ? g : 0;
    const int subc = (sub < 5) ? sub : 0;
    int e0 = start;

    for (; e0 + 30 <= end; e0 += 30) {
        int col = 0;
        if (lane < 30) col = g_col[e0 + lane];
        int srcs[5];
#pragma unroll
        for (int it = 0; it < 5; it++)
            srcs[it] = __shfl_sync(0xFFFFFFFFu, col, it * 6 + gl);
        uint4 us[5];
#pragma unroll
        for (int it = 0; it < 5; it++)
            us[it] = cur[(size_t)srcs[it] * RS + subc];
#pragma unroll
        for (int it = 0; it < 5; it++) {
            float v[8];
            unpack8(us[it], v);
            if (grp) {
#pragma unroll
                for (int j = 0; j < 8; j++) acc[j] += v[j];
            }
        }
    }
    for (; e0 < end; e0 += 6) {
        int col = 0;
        if (lane < 6) {
            int li = e0 + lane;
            col = g_col[li < end ? li : end - 1];
        }
        int src = __shfl_sync(0xFFFFFFFFu, col, gl);
        float wv = (grp && (e0 + g < end)) ? 1.f : 0.f;
        uint4 u = cur[(size_t)src * RS + subc];
        float v[8];
        unpack8(u, v);
#pragma unroll
        for (int j = 0; j < 8; j++) acc[j] += wv * v[j];
    }

    // reduce 6 groups (stride-5 lanes) -> lanes 0..4
#pragma unroll
    for (int j = 0; j < 8; j++) {
        float v = acc[j];
        v += __shfl_down_sync(0xFFFFFFFFu, v, 15);
        float t1 = __shfl_down_sync(0xFFFFFFFFu, v, 5);
        float t2 = __shfl_down_sync(0xFFFFFFFFu, v, 10);
        acc[j] = v + t1 + t2;
    }

    const float tk = temp[k + 1];
    float h[8];
#pragma unroll
    for (int j = 0; j < 8; j++) h[j] = 0.f;
    if (lane < 5) {
#pragma unroll
        for (int j = 0; j < 8; j++) acc[j] *= di;         // nv = di * (sum + s_i)
        if (FIRST) {
            const float t0z = temp[0] / di;                // z = s / di
#pragma unroll
            for (int j = 0; j < 8; j++) h[j] = t0z * c[j] + tk * acc[j];
        } else {
            float hp[8];
            unpack8(g_hiddenh[i * 5 + lane], hp);
#pragma unroll
            for (int j = 0; j < 8; j++) h[j] = hp[j] + tk * acc[j];
        }
        if (!LAST) {
            float sc[8];
#pragma unroll
            for (int j = 0; j < 8; j++) sc[j] = di * acc[j];   // s' = di * nv
            next[(size_t)i * RS + lane] = pack8(sc);
            g_hiddenh[i * 5 + lane] = pack8(h);
        }
    }
    if (LAST) {
        float m = -1e30f;
        if (lane < 5) {
#pragma unroll
            for (int j = 0; j < 8; j++) m = fmaxf(m, h[j]);
        }
#pragma unroll
        for (int o = 1; o < 8; o <<= 1) m = fmaxf(m, __shfl_xor_sync(0xFFFFFFFFu, m, o));
        float s = 0.f;
        if (lane < 5) {
#pragma unroll
            for (int j = 0; j < 8; j++) s += expf(h[j] - m);
        }
#pragma unroll
        for (int o = 1; o < 8; o <<= 1) s += __shfl_xor_sync(0xFFFFFFFFu, s, o);
        const float lse = m + logf(s);
        if (lane < 5) {
            float4* o4 = (float4*)(out + (size_t)i * OUT_CH + lane * 8);
            o4[0] = make_float4(h[0] - lse, h[1] - lse, h[2] - lse, h[3] - lse);
            o4[1] = make_float4(h[4] - lse, h[5] - lse, h[6] - lse, h[7] - lse);
        }
    }
}

// ---------------- launch: kernel launches ONLY ----------------
extern "C" void kernel_launch(void* const* d_in, const int* in_sizes, int n_in,
                              void* d_out, int out_size) {
    const float* x    = (const float*)d_in[0];
    const int*   ei   = (const int*)d_in[1];  // [2, N_EDGES] int32
    const float* W1   = (const float*)d_in[2];
    const float* b1   = (const float*)d_in[3];
    const float* W2   = (const float*)d_in[4];
    const float* b2   = (const float*)d_in[5];
    const float* gam  = (const float*)d_in[6];
    const float* bet  = (const float*)d_in[7];
    const float* mea  = (const float*)d_in[8];
    const float* var  = (const float*)d_in[9];
    const float* temp = (const float*)d_in[10];
    float* out = (float*)d_out;
    const int* srcp = ei;
    const int* dstp = ei + N_EDGES;

    // CSR first (stem needs g_dinv)
    zero_kernel<<<(N_NODES + 255) / 256, 256>>>();
    hist_kernel<<<(N_EDGES + 255) / 256, 256>>>(dstp);
    scan1_kernel<<<NB_SCAN, 1024>>>();
    scan3_kernel<<<(N_NODES + 1023) / 1024, 1024>>>();
    fill_kernel<<<(N_EDGES + 255) / 256, 256>>>(srcp, dstp);

    stem_kernel<<<(N_NODES + 127) / 128, 256>>>(x, W1, b1, W2, b2, gam, bet, mea, var);

    const int pgrid = (N_NODES * 32 + 63) / 64;
    prop_kernel<true, false><<<pgrid, 64>>>(nullptr, temp, 0);
    for (int k = 1; k < K_HOPS - 1; k++)
        prop_kernel<false, false><<<pgrid, 64>>>(nullptr, temp, k);
    prop_kernel<false, true><<<pgrid, 64>>>(out, temp, K_HOPS - 1);
}